// round 15
// baseline (speedup 1.0000x reference)
#include <cuda_runtime.h>
#include <cuda_fp16.h>
#include <math.h>
#include <stdint.h>

// Problem constants
#define Lc   6
#define Dc   1024
#define Hc   16
#define DHc  64
#define FFc  4096
#define Bc   8
#define Nc   512
#define Mrows (Bc*Nc)          // 4096
#define EPSc 1e-12f

// ------------------------------------------------------------------
// Scratch (device globals)
// ------------------------------------------------------------------
__device__ float g_x [Mrows*Dc];
__device__ float g_t [Mrows*Dc];

__device__ __half g_x16[Mrows*Dc];
__device__ __half g_e16[Mrows*Dc];
__device__ __half g_qk16[(size_t)Mrows*2*Dc];   // fused QK [4096][2048]
__device__ __half g_vt16[(size_t)Dc*Mrows];     // V^T [1024 dh_global][4096 tok]
__device__ __half g_ao16[Mrows*Dc];
__device__ __half g_ff16[(size_t)Mrows*FFc];
__device__ __half g_bias16[(size_t)Bc*Nc*Nc];   // mask additive bias fp16

// transposed fp16 weights (built once per launch)
__device__ __half g_wsa[(size_t)Lc*4*Dc*Dc];
__device__ __half g_wca[(size_t)Lc*4*Dc*Dc];
__device__ __half g_w1t[(size_t)Lc*Dc*FFc];
__device__ __half g_w2t[(size_t)Lc*FFc*Dc];

// per-(call,row-block) tile-completion counters for gemm_ln: 18 x 32
__device__ int g_cnt[18 * 32];
// per-call prep-completion counters for mega attention kernel: 12
__device__ int g_sync[12];

// ------------------------------------------------------------------
// PTX helpers
// ------------------------------------------------------------------
__device__ __forceinline__ uint32_t smem_u32(const void* p) {
    uint32_t a;
    asm("{ .reg .u64 t; cvta.to.shared.u64 t, %1; cvt.u32.u64 %0, t; }" : "=r"(a) : "l"(p));
    return a;
}
__device__ __forceinline__ void cp16(uint32_t dst, const void* src) {
    asm volatile("cp.async.cg.shared.global [%0], [%1], 16;" :: "r"(dst), "l"(src) : "memory");
}
#define CP_COMMIT() asm volatile("cp.async.commit_group;" ::: "memory")

__device__ __forceinline__ void ldsm4(uint32_t& r0, uint32_t& r1, uint32_t& r2, uint32_t& r3, uint32_t addr) {
    asm volatile("ldmatrix.sync.aligned.m8n8.x4.shared.b16 {%0,%1,%2,%3}, [%4];"
        : "=r"(r0), "=r"(r1), "=r"(r2), "=r"(r3) : "r"(addr));
}
__device__ __forceinline__ void mma16816(float* c, const uint32_t* a, uint32_t b0, uint32_t b1) {
    asm volatile(
        "mma.sync.aligned.m16n8k16.row.col.f32.f16.f16.f32 "
        "{%0,%1,%2,%3}, {%4,%5,%6,%7}, {%8,%9}, {%0,%1,%2,%3};"
        : "+f"(c[0]), "+f"(c[1]), "+f"(c[2]), "+f"(c[3])
        : "r"(a[0]), "r"(a[1]), "r"(a[2]), "r"(a[3]), "r"(b0), "r"(b1));
}
__device__ __forceinline__ uint32_t packh2(float a, float b) {
    __half2 h = __floats2half2_rn(a, b);
    return *(uint32_t*)&h;
}

// ==================================================================
// GEMM tile body (BM=128, BN=128, BK=64, 3-stage cp.async, 256 thr)
// ==================================================================
#define GEMM_STAGE 36864
#define GEMM_SMEM  (3 * GEMM_STAGE)
#define GEMM_BOFF  18432

__device__ __forceinline__ void cp_stage_g(uint32_t sbase,
    const __half* __restrict__ A, const __half* __restrict__ B,
    int m0, int n0, int k0, int K, int tid)
{
#pragma unroll
    for (int j = 0; j < 4; j++) {
        int idx = tid + 256 * j;
        int row = idx >> 3;
        int c = idx & 7;
        uint32_t d = (uint32_t)(row * 144 + c * 16);
        cp16(sbase + d,             A + (size_t)(m0 + row) * K + k0 + c * 8);
        cp16(sbase + GEMM_BOFF + d, B + (size_t)(n0 + row) * K + k0 + c * 8);
    }
}

template<bool RELU, bool HOUT>
__device__ __forceinline__ void gemm_body(
    const __half* __restrict__ A, const __half* __restrict__ B,
    const float* __restrict__ bias, int biasRow,
    const float* __restrict__ resid,
    void* __restrict__ Cout, int M, int N, int K, int m0, int n0, uint32_t sb)
{
    const int tid = threadIdx.x;
    const int wid = tid >> 5;
    const int l = tid & 31;
    const int wm = (wid >> 1) * 32;
    const int wn = (wid & 1) * 64;
    const int KT = K >> 6;

    float c[2][8][4];
#pragma unroll
    for (int i = 0; i < 2; i++)
#pragma unroll
        for (int j = 0; j < 8; j++)
#pragma unroll
            for (int r = 0; r < 4; r++) c[i][j][r] = 0.f;

#pragma unroll
    for (int s = 0; s < 2; s++) {
        cp_stage_g(sb + s * GEMM_STAGE, A, B, m0, n0, s * 64, K, tid);
        CP_COMMIT();
    }

    const uint32_t aoff = (uint32_t)((wm + (l & 15)) * 144 + (l >> 4) * 16);
    const uint32_t boff = (uint32_t)((wn + (l & 7) + ((l >> 3) & 1) * 8) * 144 + (l >> 4) * 16);

    int stage = 0;
    for (int kt = 0; kt < KT; kt++) {
        asm volatile("cp.async.wait_group 1;" ::: "memory");
        __syncthreads();

        const int pf = kt + 2;
        int pstage = stage + 2; if (pstage >= 3) pstage -= 3;
        if (pf < KT) cp_stage_g(sb + pstage * GEMM_STAGE, A, B, m0, n0, pf * 64, K, tid);
        CP_COMMIT();

        const uint32_t sA = sb + stage * GEMM_STAGE;
        const uint32_t sB = sA + GEMM_BOFF;

#pragma unroll
        for (int kk = 0; kk < 4; kk++) {
            uint32_t a[2][4], b[4][4];
            ldsm4(a[0][0], a[0][1], a[0][2], a[0][3], sA + aoff + kk * 32);
            ldsm4(a[1][0], a[1][1], a[1][2], a[1][3], sA + aoff + 16 * 144 + kk * 32);
#pragma unroll
            for (int j = 0; j < 4; j++)
                ldsm4(b[j][0], b[j][1], b[j][2], b[j][3], sB + boff + j * 16 * 144 + kk * 32);
#pragma unroll
            for (int mi = 0; mi < 2; mi++)
#pragma unroll
                for (int nj = 0; nj < 8; nj++)
                    mma16816(c[mi][nj], a[mi], b[nj >> 1][nj & 1], b[nj >> 1][(nj & 1) + 2]);
        }
        if (++stage == 3) stage = 0;
    }

    const int row0 = m0 + wm + (l >> 2);
    const int colb = n0 + wn + (l & 3) * 2;
#pragma unroll
    for (int mi = 0; mi < 2; mi++) {
        const int r0 = row0 + mi * 16;
        float br0 = 0.f, br1 = 0.f;
        if (biasRow) { br0 = bias[r0]; br1 = bias[r0 + 8]; }
#pragma unroll
        for (int nj = 0; nj < 8; nj++) {
            const int col = colb + nj * 8;
            float b0, b1, b2, b3;
            if (biasRow) {
                b0 = br0; b1 = br0; b2 = br1; b3 = br1;
            } else {
                b0 = bias[col]; b1 = bias[col + 1]; b2 = b0; b3 = b1;
            }
            float v0 = c[mi][nj][0] + b0;
            float v1 = c[mi][nj][1] + b1;
            float v2 = c[mi][nj][2] + b2;
            float v3 = c[mi][nj][3] + b3;
            if (RELU) {
                v0 = fmaxf(v0, 0.f); v1 = fmaxf(v1, 0.f);
                v2 = fmaxf(v2, 0.f); v3 = fmaxf(v3, 0.f);
            }
            if (HOUT) {
                __half* C = (__half*)Cout;
                *(__half2*)&C[(size_t)r0 * N + col]       = __floats2half2_rn(v0, v1);
                *(__half2*)&C[(size_t)(r0 + 8) * N + col] = __floats2half2_rn(v2, v3);
            } else {
                float* C = (float*)Cout;
                if (resid != nullptr) {
                    float2 x0 = *(const float2*)&resid[(size_t)r0 * N + col];
                    float2 x1 = *(const float2*)&resid[(size_t)(r0 + 8) * N + col];
                    v0 += x0.x; v1 += x0.y; v2 += x1.x; v3 += x1.y;
                }
                float2 p0; p0.x = v0; p0.y = v1;
                float2 p1; p1.x = v2; p1.y = v3;
                *(float2*)&C[(size_t)r0 * N + col] = p0;
                *(float2*)&C[(size_t)(r0 + 8) * N + col] = p1;
            }
        }
    }
}

// Standard GEMM kernel wrapper
template<bool RELU, bool HOUT>
__global__ void __launch_bounds__(256, 2)
gemm_mma_kernel(const __half* __restrict__ A, const __half* __restrict__ B,
                const float* __restrict__ bias, const float* __restrict__ resid,
                void* __restrict__ Cout, int M, int N, int K)
{
    extern __shared__ char sm_[];
    const uint32_t sb = smem_u32(sm_);
    gemm_body<RELU, HOUT>(A, B, bias, 0, resid, Cout,
                          M, N, K, blockIdx.y * 128, blockIdx.x * 128, sb);
}

// ==================================================================
// Fused GEMM (+residual) + distributed LayerNorm (grid (8,32)=256 CTAs,
// all co-resident -> spin safe).
// ==================================================================
__global__ void __launch_bounds__(256, 2)
gemm_ln_kernel(const __half* __restrict__ A, const __half* __restrict__ B,
               const float* __restrict__ bias, const float* __restrict__ resid,
               float* __restrict__ T, int M, int K,
               const float* __restrict__ gamma, const float* __restrict__ beta,
               float* __restrict__ xout, __half* __restrict__ x16out,
               int* __restrict__ cnt)
{
    extern __shared__ char sm_[];
    const uint32_t sb = smem_u32(sm_);
    const int m0 = blockIdx.y * 128;
    gemm_body<false, false>(A, B, bias, 0, resid, T,
                            M, Dc, K, m0, blockIdx.x * 128, sb);

    __threadfence();
    if (threadIdx.x == 0) {
        atomicAdd(&cnt[blockIdx.y], 1);
        while (atomicAdd(&cnt[blockIdx.y], 0) < 8) { }
    }
    __syncthreads();
    __threadfence();

    const int w = threadIdx.x >> 5;
    const int l = threadIdx.x & 31;
    const int rbase = m0 + blockIdx.x * 16;
#pragma unroll
    for (int i = 0; i < 2; i++) {
        const int row = rbase + w * 2 + i;
        const float* tr = T + (size_t)row * Dc;
        float4 v[8];
        float s = 0.f, ss = 0.f;
#pragma unroll
        for (int j = 0; j < 8; j++) {
            v[j] = *(const float4*)&tr[l * 4 + j * 128];
            s  += v[j].x + v[j].y + v[j].z + v[j].w;
            ss += v[j].x * v[j].x + v[j].y * v[j].y + v[j].z * v[j].z + v[j].w * v[j].w;
        }
#pragma unroll
        for (int o = 16; o > 0; o >>= 1) {
            s  += __shfl_xor_sync(0xffffffffu, s, o);
            ss += __shfl_xor_sync(0xffffffffu, ss, o);
        }
        const float mean = s * (1.f / Dc);
        const float var = ss * (1.f / Dc) - mean * mean;
        const float inv = rsqrtf(var + EPSc);
#pragma unroll
        for (int j = 0; j < 8; j++) {
            const int c = l * 4 + j * 128;
            float4 g4 = *(const float4*)&gamma[c];
            float4 b4 = *(const float4*)&beta[c];
            float4 o4;
            o4.x = g4.x * (v[j].x - mean) * inv + b4.x;
            o4.y = g4.y * (v[j].y - mean) * inv + b4.y;
            o4.z = g4.z * (v[j].z - mean) * inv + b4.z;
            o4.w = g4.w * (v[j].w - mean) * inv + b4.w;
            *(float4*)&xout[(size_t)row * Dc + c] = o4;
            *(__half2*)&x16out[(size_t)row * Dc + c]     = __floats2half2_rn(o4.x, o4.y);
            *(__half2*)&x16out[(size_t)row * Dc + c + 2] = __floats2half2_rn(o4.z, o4.w);
        }
    }
}

// ==================================================================
// Flash attention body (device function). Q/K from qk16 (stride 2048),
// VT rows strided vtStride.
// ==================================================================
#define FL_K_OFF 18432
#define FL_V_OFF 9216

__device__ __forceinline__ void flash_body(
    const __half* __restrict__ Qg, int qStride,
    const __half* __restrict__ Kg, int kStride,
    const __half* __restrict__ VTg, int vtStride,
    const __half* __restrict__ biasMask,
    __half* __restrict__ O, int q0, int bh, uint32_t sb)
{
    const int tid = threadIdx.x;
    const int wid = tid >> 5;
    const int l = tid & 31;
    const int b = bh >> 4;
    const int h = bh & 15;
    const int wm = wid * 16;

    const __half* Qb = Qg + h * DHc;
    const __half* Kb = Kg + h * DHc;
    const __half* VTb = VTg + (size_t)(h * DHc) * vtStride + b * Nc;

    const uint32_t sQ = sb;

#pragma unroll
    for (int j = 0; j < 4; j++) {
        int idx = tid + 256 * j;
        int row = idx >> 3;
        int c = idx & 7;
        cp16(sQ + (uint32_t)(row * 144 + c * 16),
             Qb + (size_t)(b * Nc + q0 + row) * qStride + c * 8);
    }
    {
        uint32_t sK = sb + FL_K_OFF;
        uint32_t sV = sK + FL_V_OFF;
#pragma unroll
        for (int j = 0; j < 2; j++) {
            int idx = tid + 256 * j;
            int row = idx >> 3;
            int c = idx & 7;
            cp16(sK + (uint32_t)(row * 144 + c * 16),
                 Kb + (size_t)(b * Nc + row) * kStride + c * 8);
            cp16(sV + (uint32_t)(row * 144 + c * 16),
                 VTb + (size_t)row * vtStride + c * 8);
        }
    }
    CP_COMMIT();

    float o[8][4];
#pragma unroll
    for (int j = 0; j < 8; j++)
#pragma unroll
        for (int r = 0; r < 4; r++) o[j][r] = 0.f;
    float mrow[2] = { -INFINITY, -INFINITY };
    float lsum[2] = { 0.f, 0.f };

    const uint32_t aoff = (uint32_t)((wm + (l & 15)) * 144 + (l >> 4) * 16);
    const uint32_t boff = (uint32_t)(((l & 7) + ((l >> 3) & 1) * 8) * 144 + (l >> 4) * 16);
    const int r0g = q0 + wm + (l >> 2);

    for (int t = 0; t < 8; t++) {
        if (t < 7) {
            uint32_t sK = sb + FL_K_OFF + ((t + 1) & 1) * FL_K_OFF;
            uint32_t sV = sK + FL_V_OFF;
            const int kv0 = (t + 1) * 64;
#pragma unroll
            for (int j = 0; j < 2; j++) {
                int idx = tid + 256 * j;
                int row = idx >> 3;
                int c = idx & 7;
                cp16(sK + (uint32_t)(row * 144 + c * 16),
                     Kb + (size_t)(b * Nc + kv0 + row) * kStride + c * 8);
                cp16(sV + (uint32_t)(row * 144 + c * 16),
                     VTb + (size_t)row * vtStride + kv0 + c * 8);
            }
            CP_COMMIT();
            asm volatile("cp.async.wait_group 1;" ::: "memory");
        } else {
            asm volatile("cp.async.wait_group 0;" ::: "memory");
        }
        __syncthreads();

        const uint32_t sK = sb + FL_K_OFF + (t & 1) * FL_K_OFF;
        const uint32_t sV = sK + FL_V_OFF;

        float s[8][4];
#pragma unroll
        for (int j = 0; j < 8; j++)
#pragma unroll
            for (int r = 0; r < 4; r++) s[j][r] = 0.f;

#pragma unroll
        for (int kk = 0; kk < 4; kk++) {
            uint32_t a[4], bf[4][4];
            ldsm4(a[0], a[1], a[2], a[3], sQ + aoff + kk * 32);
#pragma unroll
            for (int j = 0; j < 4; j++)
                ldsm4(bf[j][0], bf[j][1], bf[j][2], bf[j][3], sK + boff + j * 16 * 144 + kk * 32);
#pragma unroll
            for (int j = 0; j < 4; j++) {
                mma16816(s[2 * j],     a, bf[j][0], bf[j][2]);
                mma16816(s[2 * j + 1], a, bf[j][1], bf[j][3]);
            }
        }

        const int colb = t * 64 + (l & 3) * 2;
        if (biasMask != nullptr) {
#pragma unroll
            for (int nj = 0; nj < 8; nj++) {
                const int col = colb + nj * 8;
                __half2 b0 = *(const __half2*)&biasMask[((size_t)b * Nc + r0g) * Nc + col];
                __half2 b1 = *(const __half2*)&biasMask[((size_t)b * Nc + r0g + 8) * Nc + col];
                s[nj][0] = s[nj][0] * 0.125f + __low2float(b0);
                s[nj][1] = s[nj][1] * 0.125f + __high2float(b0);
                s[nj][2] = s[nj][2] * 0.125f + __low2float(b1);
                s[nj][3] = s[nj][3] * 0.125f + __high2float(b1);
            }
        } else {
#pragma unroll
            for (int nj = 0; nj < 8; nj++) {
                s[nj][0] *= 0.125f; s[nj][1] *= 0.125f;
                s[nj][2] *= 0.125f; s[nj][3] *= 0.125f;
            }
        }

        float m0 = -INFINITY, m1 = -INFINITY;
#pragma unroll
        for (int nj = 0; nj < 8; nj++) {
            m0 = fmaxf(m0, fmaxf(s[nj][0], s[nj][1]));
            m1 = fmaxf(m1, fmaxf(s[nj][2], s[nj][3]));
        }
        m0 = fmaxf(m0, __shfl_xor_sync(0xffffffffu, m0, 1));
        m0 = fmaxf(m0, __shfl_xor_sync(0xffffffffu, m0, 2));
        m1 = fmaxf(m1, __shfl_xor_sync(0xffffffffu, m1, 1));
        m1 = fmaxf(m1, __shfl_xor_sync(0xffffffffu, m1, 2));

        const float mn0 = fmaxf(mrow[0], m0);
        const float mn1 = fmaxf(mrow[1], m1);
        const float sc0 = __expf(mrow[0] - mn0);
        const float sc1 = __expf(mrow[1] - mn1);
        mrow[0] = mn0; mrow[1] = mn1;

        float rs0 = 0.f, rs1 = 0.f;
#pragma unroll
        for (int nj = 0; nj < 8; nj++) {
            s[nj][0] = __expf(s[nj][0] - mn0);
            s[nj][1] = __expf(s[nj][1] - mn0);
            s[nj][2] = __expf(s[nj][2] - mn1);
            s[nj][3] = __expf(s[nj][3] - mn1);
            rs0 += s[nj][0] + s[nj][1];
            rs1 += s[nj][2] + s[nj][3];
        }
        rs0 += __shfl_xor_sync(0xffffffffu, rs0, 1);
        rs0 += __shfl_xor_sync(0xffffffffu, rs0, 2);
        rs1 += __shfl_xor_sync(0xffffffffu, rs1, 1);
        rs1 += __shfl_xor_sync(0xffffffffu, rs1, 2);
        lsum[0] = lsum[0] * sc0 + rs0;
        lsum[1] = lsum[1] * sc1 + rs1;

#pragma unroll
        for (int j = 0; j < 8; j++) {
            o[j][0] *= sc0; o[j][1] *= sc0;
            o[j][2] *= sc1; o[j][3] *= sc1;
        }

#pragma unroll
        for (int kk = 0; kk < 4; kk++) {
            uint32_t a[4];
            a[0] = packh2(s[2 * kk][0],     s[2 * kk][1]);
            a[1] = packh2(s[2 * kk][2],     s[2 * kk][3]);
            a[2] = packh2(s[2 * kk + 1][0], s[2 * kk + 1][1]);
            a[3] = packh2(s[2 * kk + 1][2], s[2 * kk + 1][3]);
            uint32_t bf[4][4];
#pragma unroll
            for (int j = 0; j < 4; j++)
                ldsm4(bf[j][0], bf[j][1], bf[j][2], bf[j][3], sV + boff + j * 16 * 144 + kk * 32);
#pragma unroll
            for (int j = 0; j < 4; j++) {
                mma16816(o[2 * j],     a, bf[j][0], bf[j][2]);
                mma16816(o[2 * j + 1], a, bf[j][1], bf[j][3]);
            }
        }
        __syncthreads();
    }

    const float inv0 = 1.f / lsum[0];
    const float inv1 = 1.f / lsum[1];
#pragma unroll
    for (int njo = 0; njo < 8; njo++) {
        const int gc = h * DHc + njo * 8 + (l & 3) * 2;
        *(__half2*)&O[(size_t)(b * Nc + r0g) * Dc + gc] =
            __floats2half2_rn(o[njo][0] * inv0, o[njo][1] * inv0);
        *(__half2*)&O[(size_t)(b * Nc + r0g + 8) * Dc + gc] =
            __floats2half2_rn(o[njo][2] * inv1, o[njo][3] * inv1);
    }
}

// ==================================================================
// Mega attention kernel: 1280 CTAs.
//   bid <  768: prep (512 QK tiles + 256 V^T tiles), then counter++
//   bid >= 768: spin until counter==768, then flash (512 CTAs)
// Prep CTAs occupy lower bids -> issued first; they never wait ->
// flash spins are bounded (no deadlock).
// ==================================================================
__global__ void __launch_bounds__(256, 2)
attn_mega_kernel(const __half* __restrict__ Aq, const __half* __restrict__ Aq2, int nSplit,
                 const __half* __restrict__ Wqk, const float* __restrict__ biasQK,
                 __half* __restrict__ qkOut,
                 const __half* __restrict__ Wv, const __half* __restrict__ Bv,
                 const float* __restrict__ biasV, __half* __restrict__ vtOut,
                 const __half* __restrict__ biasMask, __half* __restrict__ O,
                 int* __restrict__ sync)
{
    extern __shared__ char sm_[];
    const uint32_t sb = smem_u32(sm_);
    const int i = blockIdx.x;
    if (i < 512) {
        const int m0 = (i >> 4) * 128;
        const int n0 = (i & 15) * 128;
        const __half* Au = (n0 >= nSplit) ? Aq2 : Aq;
        gemm_body<false, true>(Au, Wqk, biasQK, 0, nullptr, qkOut,
                               Mrows, 2 * Dc, Dc, m0, n0, sb);
        __threadfence();
        __syncthreads();
        if (threadIdx.x == 0) atomicAdd(sync, 1);
    } else if (i < 768) {
        const int j = i - 512;
        const int n0 = (j & 31) * 128;
        const int m0 = (j >> 5) * 128;
        gemm_body<false, true>(Wv, Bv, biasV, 1, nullptr, vtOut,
                               Dc, Mrows, Dc, m0, n0, sb);
        __threadfence();
        __syncthreads();
        if (threadIdx.x == 0) atomicAdd(sync, 1);
    } else {
        const int j = i - 768;
        const int q0 = (j & 3) * 128;
        const int bh = j >> 2;
        if (threadIdx.x == 0) {
            while (atomicAdd(sync, 0) < 768) { __nanosleep(64); }
        }
        __syncthreads();
        __threadfence();
        flash_body(qkOut, 2 * Dc, qkOut + Dc, 2 * Dc, vtOut, Mrows,
                   biasMask, O, q0, bh, sb);
    }
}

// ==================================================================
// Mask -> fp16 additive bias (0 / -10000)
// ==================================================================
__global__ void __launch_bounds__(256)
maskbias_kernel(const int* __restrict__ mask, __half* __restrict__ bias, int n)
{
    int i = (blockIdx.x * 256 + threadIdx.x) * 4;
    if (i >= n) return;
    int4 m = *(const int4*)(mask + i);
    __half z = __float2half(0.f), neg = __float2half(-10000.f);
    bias[i]     = m.x ? z : neg;
    bias[i + 1] = m.y ? z : neg;
    bias[i + 2] = m.z ? z : neg;
    bias[i + 3] = m.w ? z : neg;
}

// ==================================================================
// Batched weight transpose+convert: W[z][K,N] fp32 -> T[z][N,K] fp16
// ==================================================================
__global__ void __launch_bounds__(256)
wt_kernel(const float* __restrict__ Wbase, __half* __restrict__ Tbase, int K, int N)
{
    __shared__ float t[64][65];
    const float* W = Wbase + (size_t)blockIdx.z * K * N;
    __half* T = Tbase + (size_t)blockIdx.z * K * N;
    const int n0 = blockIdx.x * 64;
    const int k0 = blockIdx.y * 64;
    const int tid = threadIdx.x;

#pragma unroll
    for (int j = 0; j < 4; j++) {
        int idx = tid + 256 * j;
        int row = idx >> 4;
        int c = (idx & 15) * 4;
        float4 v = *(const float4*)&W[(size_t)(k0 + row) * N + n0 + c];
        t[row][c + 0] = v.x; t[row][c + 1] = v.y;
        t[row][c + 2] = v.z; t[row][c + 3] = v.w;
    }
    __syncthreads();

#pragma unroll
    for (int j = 0; j < 8; j++) {
        int idx = tid + 256 * j;
        int n = idx >> 5;
        int kp = idx & 31;
        __half2 h = __floats2half2_rn(t[2 * kp][n], t[2 * kp + 1][n]);
        *(__half2*)&T[(size_t)(n0 + n) * K + k0 + 2 * kp] = h;
    }
}

// ------------------------------------------------------------------
// misc
// ------------------------------------------------------------------
__global__ void __launch_bounds__(256)
initx_kernel(const float* __restrict__ in, float* __restrict__ x,
             __half* __restrict__ x16, int n)
{
    int i = (blockIdx.x * 256 + threadIdx.x) * 4;
    if (i >= n) return;
    float4 v = *(const float4*)(in + i);
    *(float4*)(x + i) = v;
    *(__half2*)(x16 + i)     = __floats2half2_rn(v.x, v.y);
    *(__half2*)(x16 + i + 2) = __floats2half2_rn(v.z, v.w);
}
__global__ void __launch_bounds__(256)
f2h_kernel(const float* __restrict__ in, __half* __restrict__ out, int n)
{
    int i = (blockIdx.x * 256 + threadIdx.x) * 4;
    if (i >= n) return;
    float4 v = *(const float4*)(in + i);
    *(__half2*)(out + i)     = __floats2half2_rn(v.x, v.y);
    *(__half2*)(out + i + 2) = __floats2half2_rn(v.z, v.w);
}

// ------------------------------------------------------------------
// Host orchestration
// ------------------------------------------------------------------
extern "C" void kernel_launch(void* const* d_in, const int* in_sizes, int n_in,
                              void* d_out, int out_size)
{
    const float* trg  = (const float*)d_in[0];
    const float* enc  = (const float*)d_in[1];
    const int*   mask = (const int*)  d_in[2];
    const float* sa_w = (const float*)d_in[3];
    const float* sa_b = (const float*)d_in[4];
    const float* ca_w = (const float*)d_in[5];
    const float* ca_b = (const float*)d_in[6];
    const float* ln_g = (const float*)d_in[7];
    const float* ln_b = (const float*)d_in[8];
    const float* w1   = (const float*)d_in[9];
    const float* b1   = (const float*)d_in[10];
    const float* w2   = (const float*)d_in[11];
    const float* b2   = (const float*)d_in[12];
    float* out = (float*)d_out;

    float *x, *t;
    __half *x16, *e16, *qk16, *vt16, *ao16, *ff16, *bias16;
    __half *wsa, *wca, *w1t, *w2t;
    int *cnt, *sync;
    cudaGetSymbolAddress((void**)&x,  g_x);
    cudaGetSymbolAddress((void**)&t,  g_t);
    cudaGetSymbolAddress((void**)&x16, g_x16);
    cudaGetSymbolAddress((void**)&e16, g_e16);
    cudaGetSymbolAddress((void**)&qk16, g_qk16);
    cudaGetSymbolAddress((void**)&vt16, g_vt16);
    cudaGetSymbolAddress((void**)&ao16, g_ao16);
    cudaGetSymbolAddress((void**)&ff16, g_ff16);
    cudaGetSymbolAddress((void**)&bias16, g_bias16);
    cudaGetSymbolAddress((void**)&wsa, g_wsa);
    cudaGetSymbolAddress((void**)&wca, g_wca);
    cudaGetSymbolAddress((void**)&w1t, g_w1t);
    cudaGetSymbolAddress((void**)&w2t, g_w2t);
    cudaGetSymbolAddress((void**)&cnt, g_cnt);
    cudaGetSymbolAddress((void**)&sync, g_sync);

    cudaFuncSetAttribute(gemm_mma_kernel<true,true>, cudaFuncAttributeMaxDynamicSharedMemorySize, GEMM_SMEM);
    cudaFuncSetAttribute(gemm_ln_kernel, cudaFuncAttributeMaxDynamicSharedMemorySize, GEMM_SMEM);
    cudaFuncSetAttribute(attn_mega_kernel, cudaFuncAttributeMaxDynamicSharedMemorySize, GEMM_SMEM);

    cudaMemsetAsync(cnt, 0, 18 * 32 * sizeof(int));
    cudaMemsetAsync(sync, 0, 12 * sizeof(int));

    const int nElem = Mrows * Dc;
    initx_kernel<<<(nElem / 4 + 255) / 256, 256>>>(trg, x, x16, nElem);
    f2h_kernel<<<(nElem / 4 + 255) / 256, 256>>>(enc, e16, nElem);
    const int nMask = Bc * Nc * Nc;
    maskbias_kernel<<<(nMask / 4 + 255) / 256, 256>>>(mask, bias16, nMask);

    wt_kernel<<<dim3(16, 16, 24), 256>>>(sa_w, wsa, Dc, Dc);
    wt_kernel<<<dim3(16, 16, 24), 256>>>(ca_w, wca, Dc, Dc);
    wt_kernel<<<dim3(64, 16, 6), 256>>>(w1, w1t, Dc, FFc);
    wt_kernel<<<dim3(16, 64, 6), 256>>>(w2, w2t, FFc, Dc);

    dim3 gProj(Dc / 128, Mrows / 128);       // (8, 32)
    dim3 gFF1(FFc / 128, Mrows / 128);       // (32, 32)
    const int gMega = 1280;                  // 768 prep + 512 flash

    int callIdx = 0, syncIdx = 0;
    for (int l = 0; l < Lc; l++) {
        const __half* Ws = wsa + (size_t)l * 4 * Dc * Dc;
        const __half* Wc = wca + (size_t)l * 4 * Dc * Dc;
        const float* Bs = sa_b + (size_t)l * 4 * Dc;
        const float* Bcp = ca_b + (size_t)l * 4 * Dc;
        float* xOutFF = (l == Lc - 1) ? out : x;

        // ===== self-attention (prep + flash fused) =====
        attn_mega_kernel<<<gMega, 256, GEMM_SMEM>>>(
            x16, x16, 1 << 28, Ws, Bs, qk16,
            Ws + 2 * Dc * Dc, x16, Bs + 2 * Dc, vt16,
            bias16, ao16, sync + syncIdx++);
        gemm_ln_kernel<<<gProj, 256, GEMM_SMEM>>>(
            ao16, Ws + 3 * Dc * Dc, Bs + 3 * Dc, x, t, Mrows, Dc,
            ln_g + ((size_t)l * 3 + 0) * Dc, ln_b + ((size_t)l * 3 + 0) * Dc, x, x16, cnt + (callIdx++) * 32);

        // ===== cross-attention (prep + flash fused) =====
        attn_mega_kernel<<<gMega, 256, GEMM_SMEM>>>(
            x16, e16, Dc, Wc, Bcp, qk16,
            Wc + 2 * Dc * Dc, e16, Bcp + 2 * Dc, vt16,
            nullptr, ao16, sync + syncIdx++);
        gemm_ln_kernel<<<gProj, 256, GEMM_SMEM>>>(
            ao16, Wc + 3 * Dc * Dc, Bcp + 3 * Dc, x, t, Mrows, Dc,
            ln_g + ((size_t)l * 3 + 1) * Dc, ln_b + ((size_t)l * 3 + 1) * Dc, x, x16, cnt + (callIdx++) * 32);

        // ===== FFN =====
        gemm_mma_kernel<true,true><<<gFF1, 256, GEMM_SMEM>>>(x16, w1t + (size_t)l * Dc * FFc, b1 + (size_t)l * FFc, nullptr, ff16, Mrows, FFc, Dc);
        gemm_ln_kernel<<<gProj, 256, GEMM_SMEM>>>(
            ff16, w2t + (size_t)l * FFc * Dc, b2 + (size_t)l * Dc, x, t, Mrows, FFc,
            ln_g + ((size_t)l * 3 + 2) * Dc, ln_b + ((size_t)l * 3 + 2) * Dc, xOutFF, x16, cnt + (callIdx++) * 32);
    }
}

// round 16
// speedup vs baseline: 1.0100x; 1.0100x over previous
#include <cuda_runtime.h>
#include <cuda_fp16.h>
#include <math.h>
#include <stdint.h>

// Problem constants
#define Lc   6
#define Dc   1024
#define Hc   16
#define DHc  64
#define FFc  4096
#define Bc   8
#define Nc   512
#define Mrows (Bc*Nc)          // 4096
#define EPSc 1e-12f

// ------------------------------------------------------------------
// Scratch (device globals)
// ------------------------------------------------------------------
__device__ float g_x [Mrows*Dc];
__device__ float g_t [Mrows*Dc];

__device__ __half g_x16[Mrows*Dc];
__device__ __half g_e16[Mrows*Dc];
__device__ __half g_qk16[(size_t)Mrows*2*Dc];   // fused QK [4096][2048]
__device__ __half g_vt16[(size_t)Dc*Mrows];     // V^T [1024 dh_global][4096 tok]
__device__ __half g_ao16[Mrows*Dc];
__device__ __half g_ff16[(size_t)Mrows*FFc];
__device__ __half g_bias16[(size_t)Bc*Nc*Nc];   // mask additive bias fp16

// transposed fp16 weights (built once per launch)
__device__ __half g_wsa[(size_t)Lc*4*Dc*Dc];
__device__ __half g_wca[(size_t)Lc*4*Dc*Dc];
__device__ __half g_w1t[(size_t)Lc*Dc*FFc];
__device__ __half g_w2t[(size_t)Lc*FFc*Dc];

// counters: 18x32 LN completion; 6x32 FFN1 row-block completion
__device__ int g_cnt[18 * 32];
__device__ int g_ffcnt[6 * 32];

// ------------------------------------------------------------------
// PTX helpers
// ------------------------------------------------------------------
__device__ __forceinline__ uint32_t smem_u32(const void* p) {
    uint32_t a;
    asm("{ .reg .u64 t; cvta.to.shared.u64 t, %1; cvt.u32.u64 %0, t; }" : "=r"(a) : "l"(p));
    return a;
}
__device__ __forceinline__ void cp16(uint32_t dst, const void* src) {
    asm volatile("cp.async.cg.shared.global [%0], [%1], 16;" :: "r"(dst), "l"(src) : "memory");
}
#define CP_COMMIT() asm volatile("cp.async.commit_group;" ::: "memory")

__device__ __forceinline__ void ldsm4(uint32_t& r0, uint32_t& r1, uint32_t& r2, uint32_t& r3, uint32_t addr) {
    asm volatile("ldmatrix.sync.aligned.m8n8.x4.shared.b16 {%0,%1,%2,%3}, [%4];"
        : "=r"(r0), "=r"(r1), "=r"(r2), "=r"(r3) : "r"(addr));
}
__device__ __forceinline__ void mma16816(float* c, const uint32_t* a, uint32_t b0, uint32_t b1) {
    asm volatile(
        "mma.sync.aligned.m16n8k16.row.col.f32.f16.f16.f32 "
        "{%0,%1,%2,%3}, {%4,%5,%6,%7}, {%8,%9}, {%0,%1,%2,%3};"
        : "+f"(c[0]), "+f"(c[1]), "+f"(c[2]), "+f"(c[3])
        : "r"(a[0]), "r"(a[1]), "r"(a[2]), "r"(a[3]), "r"(b0), "r"(b1));
}
__device__ __forceinline__ uint32_t packh2(float a, float b) {
    __half2 h = __floats2half2_rn(a, b);
    return *(uint32_t*)&h;
}

// ==================================================================
// GEMM tile body (BM=128, BN=128, BK=64, 3-stage cp.async, 256 thr)
// ==================================================================
#define GEMM_STAGE 36864
#define GEMM_SMEM  (3 * GEMM_STAGE)
#define GEMM_BOFF  18432

__device__ __forceinline__ void cp_stage_g(uint32_t sbase,
    const __half* __restrict__ A, const __half* __restrict__ B,
    int m0, int n0, int k0, int K, int tid)
{
#pragma unroll
    for (int j = 0; j < 4; j++) {
        int idx = tid + 256 * j;
        int row = idx >> 3;
        int c = idx & 7;
        uint32_t d = (uint32_t)(row * 144 + c * 16);
        cp16(sbase + d,             A + (size_t)(m0 + row) * K + k0 + c * 8);
        cp16(sbase + GEMM_BOFF + d, B + (size_t)(n0 + row) * K + k0 + c * 8);
    }
}

template<bool RELU, bool HOUT>
__device__ __forceinline__ void gemm_body(
    const __half* __restrict__ A, const __half* __restrict__ B,
    const float* __restrict__ bias, int biasRow,
    const float* __restrict__ resid,
    void* __restrict__ Cout, int M, int N, int K, int m0, int n0, uint32_t sb)
{
    const int tid = threadIdx.x;
    const int wid = tid >> 5;
    const int l = tid & 31;
    const int wm = (wid >> 1) * 32;
    const int wn = (wid & 1) * 64;
    const int KT = K >> 6;

    float c[2][8][4];
#pragma unroll
    for (int i = 0; i < 2; i++)
#pragma unroll
        for (int j = 0; j < 8; j++)
#pragma unroll
            for (int r = 0; r < 4; r++) c[i][j][r] = 0.f;

#pragma unroll
    for (int s = 0; s < 2; s++) {
        cp_stage_g(sb + s * GEMM_STAGE, A, B, m0, n0, s * 64, K, tid);
        CP_COMMIT();
    }

    const uint32_t aoff = (uint32_t)((wm + (l & 15)) * 144 + (l >> 4) * 16);
    const uint32_t boff = (uint32_t)((wn + (l & 7) + ((l >> 3) & 1) * 8) * 144 + (l >> 4) * 16);

    int stage = 0;
    for (int kt = 0; kt < KT; kt++) {
        asm volatile("cp.async.wait_group 1;" ::: "memory");
        __syncthreads();

        const int pf = kt + 2;
        int pstage = stage + 2; if (pstage >= 3) pstage -= 3;
        if (pf < KT) cp_stage_g(sb + pstage * GEMM_STAGE, A, B, m0, n0, pf * 64, K, tid);
        CP_COMMIT();

        const uint32_t sA = sb + stage * GEMM_STAGE;
        const uint32_t sB = sA + GEMM_BOFF;

#pragma unroll
        for (int kk = 0; kk < 4; kk++) {
            uint32_t a[2][4], b[4][4];
            ldsm4(a[0][0], a[0][1], a[0][2], a[0][3], sA + aoff + kk * 32);
            ldsm4(a[1][0], a[1][1], a[1][2], a[1][3], sA + aoff + 16 * 144 + kk * 32);
#pragma unroll
            for (int j = 0; j < 4; j++)
                ldsm4(b[j][0], b[j][1], b[j][2], b[j][3], sB + boff + j * 16 * 144 + kk * 32);
#pragma unroll
            for (int mi = 0; mi < 2; mi++)
#pragma unroll
                for (int nj = 0; nj < 8; nj++)
                    mma16816(c[mi][nj], a[mi], b[nj >> 1][nj & 1], b[nj >> 1][(nj & 1) + 2]);
        }
        if (++stage == 3) stage = 0;
    }

    const int row0 = m0 + wm + (l >> 2);
    const int colb = n0 + wn + (l & 3) * 2;
#pragma unroll
    for (int mi = 0; mi < 2; mi++) {
        const int r0 = row0 + mi * 16;
        float br0 = 0.f, br1 = 0.f;
        if (biasRow) { br0 = bias[r0]; br1 = bias[r0 + 8]; }
#pragma unroll
        for (int nj = 0; nj < 8; nj++) {
            const int col = colb + nj * 8;
            float b0, b1, b2, b3;
            if (biasRow) {
                b0 = br0; b1 = br0; b2 = br1; b3 = br1;
            } else {
                b0 = bias[col]; b1 = bias[col + 1]; b2 = b0; b3 = b1;
            }
            float v0 = c[mi][nj][0] + b0;
            float v1 = c[mi][nj][1] + b1;
            float v2 = c[mi][nj][2] + b2;
            float v3 = c[mi][nj][3] + b3;
            if (RELU) {
                v0 = fmaxf(v0, 0.f); v1 = fmaxf(v1, 0.f);
                v2 = fmaxf(v2, 0.f); v3 = fmaxf(v3, 0.f);
            }
            if (HOUT) {
                __half* C = (__half*)Cout;
                *(__half2*)&C[(size_t)r0 * N + col]       = __floats2half2_rn(v0, v1);
                *(__half2*)&C[(size_t)(r0 + 8) * N + col] = __floats2half2_rn(v2, v3);
            } else {
                float* C = (float*)Cout;
                if (resid != nullptr) {
                    float2 x0 = *(const float2*)&resid[(size_t)r0 * N + col];
                    float2 x1 = *(const float2*)&resid[(size_t)(r0 + 8) * N + col];
                    v0 += x0.x; v1 += x0.y; v2 += x1.x; v3 += x1.y;
                }
                float2 p0; p0.x = v0; p0.y = v1;
                float2 p1; p1.x = v2; p1.y = v3;
                *(float2*)&C[(size_t)r0 * N + col] = p0;
                *(float2*)&C[(size_t)(r0 + 8) * N + col] = p1;
            }
        }
    }
}

// ==================================================================
// Distributed LN tail (8 col-tile CTAs per 128-row block).
// Caller guarantees the 8 CTAs become co-resident.
// ==================================================================
__device__ __forceinline__ void ln_tail(
    const float* __restrict__ T, int m0, int nb,
    const float* __restrict__ gamma, const float* __restrict__ beta,
    float* __restrict__ xout, __half* __restrict__ x16out,
    int* __restrict__ cnt)
{
    __threadfence();
    __syncthreads();
    if (threadIdx.x == 0) {
        atomicAdd(cnt, 1);
        while (atomicAdd(cnt, 0) < 8) { }
    }
    __syncthreads();
    __threadfence();

    const int w = threadIdx.x >> 5;
    const int l = threadIdx.x & 31;
    const int rbase = m0 + nb * 16;
#pragma unroll
    for (int i = 0; i < 2; i++) {
        const int row = rbase + w * 2 + i;
        const float* tr = T + (size_t)row * Dc;
        float4 v[8];
        float s = 0.f, ss = 0.f;
#pragma unroll
        for (int j = 0; j < 8; j++) {
            v[j] = *(const float4*)&tr[l * 4 + j * 128];
            s  += v[j].x + v[j].y + v[j].z + v[j].w;
            ss += v[j].x * v[j].x + v[j].y * v[j].y + v[j].z * v[j].z + v[j].w * v[j].w;
        }
#pragma unroll
        for (int o = 16; o > 0; o >>= 1) {
            s  += __shfl_xor_sync(0xffffffffu, s, o);
            ss += __shfl_xor_sync(0xffffffffu, ss, o);
        }
        const float mean = s * (1.f / Dc);
        const float var = ss * (1.f / Dc) - mean * mean;
        const float inv = rsqrtf(var + EPSc);
#pragma unroll
        for (int j = 0; j < 8; j++) {
            const int c = l * 4 + j * 128;
            float4 g4 = *(const float4*)&gamma[c];
            float4 b4 = *(const float4*)&beta[c];
            float4 o4;
            o4.x = g4.x * (v[j].x - mean) * inv + b4.x;
            o4.y = g4.y * (v[j].y - mean) * inv + b4.y;
            o4.z = g4.z * (v[j].z - mean) * inv + b4.z;
            o4.w = g4.w * (v[j].w - mean) * inv + b4.w;
            *(float4*)&xout[(size_t)row * Dc + c] = o4;
            *(__half2*)&x16out[(size_t)row * Dc + c]     = __floats2half2_rn(o4.x, o4.y);
            *(__half2*)&x16out[(size_t)row * Dc + c + 2] = __floats2half2_rn(o4.z, o4.w);
        }
    }
}

// ==================================================================
// Fused GEMM (+residual) + distributed LayerNorm. Grid (8,32)=256 CTAs.
// ==================================================================
__global__ void __launch_bounds__(256, 2)
gemm_ln_kernel(const __half* __restrict__ A, const __half* __restrict__ B,
               const float* __restrict__ bias, const float* __restrict__ resid,
               float* __restrict__ T, int M, int K,
               const float* __restrict__ gamma, const float* __restrict__ beta,
               float* __restrict__ xout, __half* __restrict__ x16out,
               int* __restrict__ cnt)
{
    extern __shared__ char sm_[];
    const uint32_t sb = smem_u32(sm_);
    const int m0 = blockIdx.y * 128;
    gemm_body<false, false>(A, B, bias, 0, resid, T,
                            M, Dc, K, m0, blockIdx.x * 128, sb);
    ln_tail(T, m0, blockIdx.x, gamma, beta, xout, x16out, &cnt[blockIdx.y]);
}

// ==================================================================
// Fused FFN: 1280 CTAs.
//  bid < 1024: FFN1 tile (ReLU, fp16 out) -> ffcnt[mb]++
//  bid >= 1024: spin ffcnt[mb]==32, FFN2 tile (+residual), LN tail.
// Producers never wait; consumers have higher bids -> no deadlock.
// ==================================================================
__global__ void __launch_bounds__(256, 2)
ffn_mega_kernel(const __half* __restrict__ x16in,
                const __half* __restrict__ W1t, const float* __restrict__ B1,
                __half* __restrict__ ff,
                const __half* __restrict__ W2t, const float* __restrict__ B2,
                const float* __restrict__ resid, float* __restrict__ T,
                const float* __restrict__ gamma, const float* __restrict__ beta,
                float* __restrict__ xout, __half* __restrict__ x16out,
                int* __restrict__ ffcnt, int* __restrict__ lncnt)
{
    extern __shared__ char sm_[];
    const uint32_t sb = smem_u32(sm_);
    const int i = blockIdx.x;
    if (i < 1024) {
        const int mb = i >> 5;
        const int nb = i & 31;
        gemm_body<true, true>(x16in, W1t, B1, 0, nullptr, ff,
                              Mrows, FFc, Dc, mb * 128, nb * 128, sb);
        __threadfence();
        __syncthreads();
        if (threadIdx.x == 0) atomicAdd(&ffcnt[mb], 1);
    } else {
        const int j = i - 1024;
        const int mb = j >> 3;
        const int nb = j & 7;
        if (threadIdx.x == 0) {
            while (atomicAdd(&ffcnt[mb], 0) < 32) { __nanosleep(64); }
        }
        __syncthreads();
        __threadfence();
        gemm_body<false, false>(ff, W2t, B2, 0, resid, T,
                                Mrows, Dc, FFc, mb * 128, nb * 128, sb);
        ln_tail(T, mb * 128, nb, gamma, beta, xout, x16out, &lncnt[mb]);
    }
}

// Merged attention prep: QK projection (512 tiles) + V^T projection (256 tiles)
__global__ void __launch_bounds__(256, 2)
attnprep_kernel(const __half* __restrict__ Aq, const __half* __restrict__ Aq2, int nSplit,
                const __half* __restrict__ Wqk, const float* __restrict__ biasQK,
                __half* __restrict__ qkOut,
                const __half* __restrict__ Wv, const __half* __restrict__ Bv,
                const float* __restrict__ biasV, __half* __restrict__ vtOut)
{
    extern __shared__ char sm_[];
    const uint32_t sb = smem_u32(sm_);
    const int i = blockIdx.x;
    if (i < 512) {
        const int m0 = (i >> 4) * 128;
        const int n0 = (i & 15) * 128;
        const __half* Au = (n0 >= nSplit) ? Aq2 : Aq;
        gemm_body<false, true>(Au, Wqk, biasQK, 0, nullptr, qkOut,
                               Mrows, 2 * Dc, Dc, m0, n0, sb);
    } else {
        const int j = i - 512;
        const int n0 = (j & 31) * 128;
        const int m0 = (j >> 5) * 128;
        gemm_body<false, true>(Wv, Bv, biasV, 1, nullptr, vtOut,
                               Dc, Mrows, Dc, m0, n0, sb);
    }
}

// ==================================================================
// Flash attention: O = softmax(Q K^T / 8 + bias) V   (__expf softmax)
// ==================================================================
#define FL_SMEM (18432 + 2 * 18432)

__global__ void __launch_bounds__(256, 2)
flash_kernel(const __half* __restrict__ Qg, int qStride,
             const __half* __restrict__ Kg, int kStride,
             const __half* __restrict__ VTg, int vtStride,
             const __half* __restrict__ biasMask,
             __half* __restrict__ O)
{
    extern __shared__ char sm_[];
    const uint32_t sb = smem_u32(sm_);
    const int tid = threadIdx.x;
    const int wid = tid >> 5;
    const int l = tid & 31;
    const int bh = blockIdx.y;
    const int b = bh >> 4;
    const int h = bh & 15;
    const int q0 = blockIdx.x * 128;
    const int wm = wid * 16;

    const __half* Qb = Qg + h * DHc;
    const __half* Kb = Kg + h * DHc;
    const __half* VTb = VTg + (size_t)(h * DHc) * vtStride + b * Nc;

    const uint32_t sQ = sb;

#pragma unroll
    for (int j = 0; j < 4; j++) {
        int idx = tid + 256 * j;
        int row = idx >> 3;
        int c = idx & 7;
        cp16(sQ + (uint32_t)(row * 144 + c * 16),
             Qb + (size_t)(b * Nc + q0 + row) * qStride + c * 8);
    }
    {
        uint32_t sK = sb + 18432;
        uint32_t sV = sK + 9216;
#pragma unroll
        for (int j = 0; j < 2; j++) {
            int idx = tid + 256 * j;
            int row = idx >> 3;
            int c = idx & 7;
            cp16(sK + (uint32_t)(row * 144 + c * 16),
                 Kb + (size_t)(b * Nc + row) * kStride + c * 8);
            cp16(sV + (uint32_t)(row * 144 + c * 16),
                 VTb + (size_t)row * vtStride + c * 8);
        }
    }
    CP_COMMIT();

    float o[8][4];
#pragma unroll
    for (int j = 0; j < 8; j++)
#pragma unroll
        for (int r = 0; r < 4; r++) o[j][r] = 0.f;
    float mrow[2] = { -INFINITY, -INFINITY };
    float lsum[2] = { 0.f, 0.f };

    const uint32_t aoff = (uint32_t)((wm + (l & 15)) * 144 + (l >> 4) * 16);
    const uint32_t boff = (uint32_t)(((l & 7) + ((l >> 3) & 1) * 8) * 144 + (l >> 4) * 16);
    const int r0g = q0 + wm + (l >> 2);

    for (int t = 0; t < 8; t++) {
        if (t < 7) {
            uint32_t sK = sb + 18432 + ((t + 1) & 1) * 18432;
            uint32_t sV = sK + 9216;
            const int kv0 = (t + 1) * 64;
#pragma unroll
            for (int j = 0; j < 2; j++) {
                int idx = tid + 256 * j;
                int row = idx >> 3;
                int c = idx & 7;
                cp16(sK + (uint32_t)(row * 144 + c * 16),
                     Kb + (size_t)(b * Nc + kv0 + row) * kStride + c * 8);
                cp16(sV + (uint32_t)(row * 144 + c * 16),
                     VTb + (size_t)row * vtStride + kv0 + c * 8);
            }
            CP_COMMIT();
            asm volatile("cp.async.wait_group 1;" ::: "memory");
        } else {
            asm volatile("cp.async.wait_group 0;" ::: "memory");
        }
        __syncthreads();

        const uint32_t sK = sb + 18432 + (t & 1) * 18432;
        const uint32_t sV = sK + 9216;

        float s[8][4];
#pragma unroll
        for (int j = 0; j < 8; j++)
#pragma unroll
            for (int r = 0; r < 4; r++) s[j][r] = 0.f;

#pragma unroll
        for (int kk = 0; kk < 4; kk++) {
            uint32_t a[4], bf[4][4];
            ldsm4(a[0], a[1], a[2], a[3], sQ + aoff + kk * 32);
#pragma unroll
            for (int j = 0; j < 4; j++)
                ldsm4(bf[j][0], bf[j][1], bf[j][2], bf[j][3], sK + boff + j * 16 * 144 + kk * 32);
#pragma unroll
            for (int j = 0; j < 4; j++) {
                mma16816(s[2 * j],     a, bf[j][0], bf[j][2]);
                mma16816(s[2 * j + 1], a, bf[j][1], bf[j][3]);
            }
        }

        const int colb = t * 64 + (l & 3) * 2;
        if (biasMask != nullptr) {
#pragma unroll
            for (int nj = 0; nj < 8; nj++) {
                const int col = colb + nj * 8;
                __half2 b0 = *(const __half2*)&biasMask[((size_t)b * Nc + r0g) * Nc + col];
                __half2 b1 = *(const __half2*)&biasMask[((size_t)b * Nc + r0g + 8) * Nc + col];
                s[nj][0] = s[nj][0] * 0.125f + __low2float(b0);
                s[nj][1] = s[nj][1] * 0.125f + __high2float(b0);
                s[nj][2] = s[nj][2] * 0.125f + __low2float(b1);
                s[nj][3] = s[nj][3] * 0.125f + __high2float(b1);
            }
        } else {
#pragma unroll
            for (int nj = 0; nj < 8; nj++) {
                s[nj][0] *= 0.125f; s[nj][1] *= 0.125f;
                s[nj][2] *= 0.125f; s[nj][3] *= 0.125f;
            }
        }

        float m0 = -INFINITY, m1 = -INFINITY;
#pragma unroll
        for (int nj = 0; nj < 8; nj++) {
            m0 = fmaxf(m0, fmaxf(s[nj][0], s[nj][1]));
            m1 = fmaxf(m1, fmaxf(s[nj][2], s[nj][3]));
        }
        m0 = fmaxf(m0, __shfl_xor_sync(0xffffffffu, m0, 1));
        m0 = fmaxf(m0, __shfl_xor_sync(0xffffffffu, m0, 2));
        m1 = fmaxf(m1, __shfl_xor_sync(0xffffffffu, m1, 1));
        m1 = fmaxf(m1, __shfl_xor_sync(0xffffffffu, m1, 2));

        const float mn0 = fmaxf(mrow[0], m0);
        const float mn1 = fmaxf(mrow[1], m1);
        const float sc0 = __expf(mrow[0] - mn0);
        const float sc1 = __expf(mrow[1] - mn1);
        mrow[0] = mn0; mrow[1] = mn1;

        float rs0 = 0.f, rs1 = 0.f;
#pragma unroll
        for (int nj = 0; nj < 8; nj++) {
            s[nj][0] = __expf(s[nj][0] - mn0);
            s[nj][1] = __expf(s[nj][1] - mn0);
            s[nj][2] = __expf(s[nj][2] - mn1);
            s[nj][3] = __expf(s[nj][3] - mn1);
            rs0 += s[nj][0] + s[nj][1];
            rs1 += s[nj][2] + s[nj][3];
        }
        rs0 += __shfl_xor_sync(0xffffffffu, rs0, 1);
        rs0 += __shfl_xor_sync(0xffffffffu, rs0, 2);
        rs1 += __shfl_xor_sync(0xffffffffu, rs1, 1);
        rs1 += __shfl_xor_sync(0xffffffffu, rs1, 2);
        lsum[0] = lsum[0] * sc0 + rs0;
        lsum[1] = lsum[1] * sc1 + rs1;

#pragma unroll
        for (int j = 0; j < 8; j++) {
            o[j][0] *= sc0; o[j][1] *= sc0;
            o[j][2] *= sc1; o[j][3] *= sc1;
        }

#pragma unroll
        for (int kk = 0; kk < 4; kk++) {
            uint32_t a[4];
            a[0] = packh2(s[2 * kk][0],     s[2 * kk][1]);
            a[1] = packh2(s[2 * kk][2],     s[2 * kk][3]);
            a[2] = packh2(s[2 * kk + 1][0], s[2 * kk + 1][1]);
            a[3] = packh2(s[2 * kk + 1][2], s[2 * kk + 1][3]);
            uint32_t bf[4][4];
#pragma unroll
            for (int j = 0; j < 4; j++)
                ldsm4(bf[j][0], bf[j][1], bf[j][2], bf[j][3], sV + boff + j * 16 * 144 + kk * 32);
#pragma unroll
            for (int j = 0; j < 4; j++) {
                mma16816(o[2 * j],     a, bf[j][0], bf[j][2]);
                mma16816(o[2 * j + 1], a, bf[j][1], bf[j][3]);
            }
        }
        __syncthreads();
    }

    const float inv0 = 1.f / lsum[0];
    const float inv1 = 1.f / lsum[1];
#pragma unroll
    for (int njo = 0; njo < 8; njo++) {
        const int gc = h * DHc + njo * 8 + (l & 3) * 2;
        *(__half2*)&O[(size_t)(b * Nc + r0g) * Dc + gc] =
            __floats2half2_rn(o[njo][0] * inv0, o[njo][1] * inv0);
        *(__half2*)&O[(size_t)(b * Nc + r0g + 8) * Dc + gc] =
            __floats2half2_rn(o[njo][2] * inv1, o[njo][3] * inv1);
    }
}

// ==================================================================
// Mask -> fp16 additive bias (0 / -10000)
// ==================================================================
__global__ void __launch_bounds__(256)
maskbias_kernel(const int* __restrict__ mask, __half* __restrict__ bias, int n)
{
    int i = (blockIdx.x * 256 + threadIdx.x) * 4;
    if (i >= n) return;
    int4 m = *(const int4*)(mask + i);
    __half z = __float2half(0.f), neg = __float2half(-10000.f);
    bias[i]     = m.x ? z : neg;
    bias[i + 1] = m.y ? z : neg;
    bias[i + 2] = m.z ? z : neg;
    bias[i + 3] = m.w ? z : neg;
}

// ==================================================================
// All weight transposes in ONE launch. Flat grid 24576 tiles of 64x64.
// ==================================================================
__device__ __forceinline__ void wt_tile(
    const float* __restrict__ W, __half* __restrict__ T,
    int K, int N, int k0, int n0)
{
    __shared__ float t[64][65];
    const int tid = threadIdx.x;
#pragma unroll
    for (int j = 0; j < 4; j++) {
        int idx = tid + 256 * j;
        int row = idx >> 4;
        int c = (idx & 15) * 4;
        float4 v = *(const float4*)&W[(size_t)(k0 + row) * N + n0 + c];
        t[row][c + 0] = v.x; t[row][c + 1] = v.y;
        t[row][c + 2] = v.z; t[row][c + 3] = v.w;
    }
    __syncthreads();
#pragma unroll
    for (int j = 0; j < 8; j++) {
        int idx = tid + 256 * j;
        int n = idx >> 5;
        int kp = idx & 31;
        __half2 h = __floats2half2_rn(t[2 * kp][n], t[2 * kp + 1][n]);
        *(__half2*)&T[(size_t)(n0 + n) * K + k0 + 2 * kp] = h;
    }
}

__global__ void __launch_bounds__(256)
wt_all_kernel(const float* __restrict__ sa_w, __half* __restrict__ wsa,
              const float* __restrict__ ca_w, __half* __restrict__ wca,
              const float* __restrict__ w1, __half* __restrict__ w1t,
              const float* __restrict__ w2, __half* __restrict__ w2t)
{
    const int i = blockIdx.x;
    if (i < 6144) {                       // sa: 24 mats of 16x16 tiles
        int z = i >> 8, r = i & 255;
        wt_tile(sa_w + (size_t)z * Dc * Dc, wsa + (size_t)z * Dc * Dc,
                Dc, Dc, (r >> 4) * 64, (r & 15) * 64);
    } else if (i < 12288) {               // ca
        int j = i - 6144;
        int z = j >> 8, r = j & 255;
        wt_tile(ca_w + (size_t)z * Dc * Dc, wca + (size_t)z * Dc * Dc,
                Dc, Dc, (r >> 4) * 64, (r & 15) * 64);
    } else if (i < 18432) {               // w1: 6 mats, K=1024,N=4096: 16x64 tiles
        int j = i - 12288;
        int z = j >> 10, r = j & 1023;
        wt_tile(w1 + (size_t)z * Dc * FFc, w1t + (size_t)z * Dc * FFc,
                Dc, FFc, (r >> 6) * 64, (r & 63) * 64);
    } else {                              // w2: 6 mats, K=4096,N=1024: 64x16 tiles
        int j = i - 18432;
        int z = j >> 10, r = j & 1023;
        wt_tile(w2 + (size_t)z * FFc * Dc, w2t + (size_t)z * FFc * Dc,
                FFc, Dc, (r >> 4) * 64, (r & 15) * 64);
    }
}

// ------------------------------------------------------------------
// misc
// ------------------------------------------------------------------
__global__ void __launch_bounds__(256)
initx_kernel(const float* __restrict__ in, float* __restrict__ x,
             __half* __restrict__ x16, int n)
{
    int i = (blockIdx.x * 256 + threadIdx.x) * 4;
    if (i >= n) return;
    float4 v = *(const float4*)(in + i);
    *(float4*)(x + i) = v;
    *(__half2*)(x16 + i)     = __floats2half2_rn(v.x, v.y);
    *(__half2*)(x16 + i + 2) = __floats2half2_rn(v.z, v.w);
}
__global__ void __launch_bounds__(256)
f2h_kernel(const float* __restrict__ in, __half* __restrict__ out, int n)
{
    int i = (blockIdx.x * 256 + threadIdx.x) * 4;
    if (i >= n) return;
    float4 v = *(const float4*)(in + i);
    *(__half2*)(out + i)     = __floats2half2_rn(v.x, v.y);
    *(__half2*)(out + i + 2) = __floats2half2_rn(v.z, v.w);
}

// ------------------------------------------------------------------
// Host orchestration
// ------------------------------------------------------------------
extern "C" void kernel_launch(void* const* d_in, const int* in_sizes, int n_in,
                              void* d_out, int out_size)
{
    const float* trg  = (const float*)d_in[0];
    const float* enc  = (const float*)d_in[1];
    const int*   mask = (const int*)  d_in[2];
    const float* sa_w = (const float*)d_in[3];
    const float* sa_b = (const float*)d_in[4];
    const float* ca_w = (const float*)d_in[5];
    const float* ca_b = (const float*)d_in[6];
    const float* ln_g = (const float*)d_in[7];
    const float* ln_b = (const float*)d_in[8];
    const float* w1   = (const float*)d_in[9];
    const float* b1   = (const float*)d_in[10];
    const float* w2   = (const float*)d_in[11];
    const float* b2   = (const float*)d_in[12];
    float* out = (float*)d_out;

    float *x, *t;
    __half *x16, *e16, *qk16, *vt16, *ao16, *ff16, *bias16;
    __half *wsa, *wca, *w1t, *w2t;
    int *cnt, *ffcnt;
    cudaGetSymbolAddress((void**)&x,  g_x);
    cudaGetSymbolAddress((void**)&t,  g_t);
    cudaGetSymbolAddress((void**)&x16, g_x16);
    cudaGetSymbolAddress((void**)&e16, g_e16);
    cudaGetSymbolAddress((void**)&qk16, g_qk16);
    cudaGetSymbolAddress((void**)&vt16, g_vt16);
    cudaGetSymbolAddress((void**)&ao16, g_ao16);
    cudaGetSymbolAddress((void**)&ff16, g_ff16);
    cudaGetSymbolAddress((void**)&bias16, g_bias16);
    cudaGetSymbolAddress((void**)&wsa, g_wsa);
    cudaGetSymbolAddress((void**)&wca, g_wca);
    cudaGetSymbolAddress((void**)&w1t, g_w1t);
    cudaGetSymbolAddress((void**)&w2t, g_w2t);
    cudaGetSymbolAddress((void**)&cnt, g_cnt);
    cudaGetSymbolAddress((void**)&ffcnt, g_ffcnt);

    cudaFuncSetAttribute(gemm_ln_kernel, cudaFuncAttributeMaxDynamicSharedMemorySize, GEMM_SMEM);
    cudaFuncSetAttribute(ffn_mega_kernel, cudaFuncAttributeMaxDynamicSharedMemorySize, GEMM_SMEM);
    cudaFuncSetAttribute(attnprep_kernel, cudaFuncAttributeMaxDynamicSharedMemorySize, GEMM_SMEM);
    cudaFuncSetAttribute(flash_kernel, cudaFuncAttributeMaxDynamicSharedMemorySize, FL_SMEM);

    cudaMemsetAsync(cnt, 0, 18 * 32 * sizeof(int));
    cudaMemsetAsync(ffcnt, 0, 6 * 32 * sizeof(int));

    const int nElem = Mrows * Dc;
    initx_kernel<<<(nElem / 4 + 255) / 256, 256>>>(trg, x, x16, nElem);
    f2h_kernel<<<(nElem / 4 + 255) / 256, 256>>>(enc, e16, nElem);
    const int nMask = Bc * Nc * Nc;
    maskbias_kernel<<<(nMask / 4 + 255) / 256, 256>>>(mask, bias16, nMask);
    wt_all_kernel<<<24576, 256>>>(sa_w, wsa, ca_w, wca, w1, w1t, w2, w2t);

    dim3 gProj(Dc / 128, Mrows / 128);       // (8, 32)
    dim3 gFlash(Nc / 128, Bc * Hc);          // (4, 128)
    const int gPrep = 768;
    const int gFFN = 1280;

    int callIdx = 0;
    for (int l = 0; l < Lc; l++) {
        const __half* Ws = wsa + (size_t)l * 4 * Dc * Dc;
        const __half* Wc = wca + (size_t)l * 4 * Dc * Dc;
        const float* Bs = sa_b + (size_t)l * 4 * Dc;
        const float* Bcp = ca_b + (size_t)l * 4 * Dc;
        float* xOutFF = (l == Lc - 1) ? out : x;

        // ===== self-attention =====
        attnprep_kernel<<<gPrep, 256, GEMM_SMEM>>>(
            x16, x16, 1 << 28, Ws, Bs, qk16,
            Ws + 2 * Dc * Dc, x16, Bs + 2 * Dc, vt16);
        flash_kernel<<<gFlash, 256, FL_SMEM>>>(qk16, 2 * Dc, qk16 + Dc, 2 * Dc, vt16, Mrows, bias16, ao16);
        gemm_ln_kernel<<<gProj, 256, GEMM_SMEM>>>(
            ao16, Ws + 3 * Dc * Dc, Bs + 3 * Dc, x, t, Mrows, Dc,
            ln_g + ((size_t)l * 3 + 0) * Dc, ln_b + ((size_t)l * 3 + 0) * Dc, x, x16, cnt + (callIdx++) * 32);

        // ===== cross-attention =====
        attnprep_kernel<<<gPrep, 256, GEMM_SMEM>>>(
            x16, e16, Dc, Wc, Bcp, qk16,
            Wc + 2 * Dc * Dc, e16, Bcp + 2 * Dc, vt16);
        flash_kernel<<<gFlash, 256, FL_SMEM>>>(qk16, 2 * Dc, qk16 + Dc, 2 * Dc, vt16, Mrows, nullptr, ao16);
        gemm_ln_kernel<<<gProj, 256, GEMM_SMEM>>>(
            ao16, Wc + 3 * Dc * Dc, Bcp + 3 * Dc, x, t, Mrows, Dc,
            ln_g + ((size_t)l * 3 + 1) * Dc, ln_b + ((size_t)l * 3 + 1) * Dc, x, x16, cnt + (callIdx++) * 32);

        // ===== FFN (FFN1 + FFN2 + LN fused, per-row-block dependency) =====
        ffn_mega_kernel<<<gFFN, 256, GEMM_SMEM>>>(
            x16, w1t + (size_t)l * Dc * FFc, b1 + (size_t)l * FFc, ff16,
            w2t + (size_t)l * FFc * Dc, b2 + (size_t)l * Dc, x, t,
            ln_g + ((size_t)l * 3 + 2) * Dc, ln_b + ((size_t)l * 3 + 2) * Dc,
            xOutFF, x16, ffcnt + l * 32, cnt + (callIdx++) * 32);
    }
}

// round 17
// speedup vs baseline: 1.0476x; 1.0372x over previous
#include <cuda_runtime.h>
#include <cuda_fp16.h>
#include <math.h>
#include <stdint.h>

// Problem constants
#define Lc   6
#define Dc   1024
#define Hc   16
#define DHc  64
#define FFc  4096
#define Bc   8
#define Nc   512
#define Mrows (Bc*Nc)          // 4096
#define EPSc 1e-12f

// ------------------------------------------------------------------
// Scratch (device globals)
// ------------------------------------------------------------------
__device__ float g_x [Mrows*Dc];
__device__ float g_t [Mrows*Dc];

__device__ __half g_x16[Mrows*Dc];
__device__ __half g_e16[Mrows*Dc];
__device__ __half g_qk16[(size_t)Mrows*2*Dc];   // fused QK [4096][2048]
__device__ __half g_vt16[(size_t)Dc*Mrows];     // V^T [1024 dh_global][4096 tok]
__device__ __half g_ao16[Mrows*Dc];
__device__ __half g_ff16[(size_t)Mrows*FFc];
__device__ __half g_bias16[(size_t)Bc*Nc*Nc];   // mask additive bias fp16

// transposed fp16 weights (built once per launch)
__device__ __half g_wsa[(size_t)Lc*4*Dc*Dc];
__device__ __half g_wca[(size_t)Lc*4*Dc*Dc];
__device__ __half g_w1t[(size_t)Lc*Dc*FFc];
__device__ __half g_w2t[(size_t)Lc*FFc*Dc];

// counters: 18x32 LN; 6x32 FFN1 row-block; 12x8 attention per-batch
__device__ int g_cnt[18 * 32];
__device__ int g_ffcnt[6 * 32];
__device__ int g_async[12 * 8];

// ------------------------------------------------------------------
// PTX helpers
// ------------------------------------------------------------------
__device__ __forceinline__ uint32_t smem_u32(const void* p) {
    uint32_t a;
    asm("{ .reg .u64 t; cvta.to.shared.u64 t, %1; cvt.u32.u64 %0, t; }" : "=r"(a) : "l"(p));
    return a;
}
__device__ __forceinline__ void cp16(uint32_t dst, const void* src) {
    asm volatile("cp.async.cg.shared.global [%0], [%1], 16;" :: "r"(dst), "l"(src) : "memory");
}
#define CP_COMMIT() asm volatile("cp.async.commit_group;" ::: "memory")

__device__ __forceinline__ void ldsm4(uint32_t& r0, uint32_t& r1, uint32_t& r2, uint32_t& r3, uint32_t addr) {
    asm volatile("ldmatrix.sync.aligned.m8n8.x4.shared.b16 {%0,%1,%2,%3}, [%4];"
        : "=r"(r0), "=r"(r1), "=r"(r2), "=r"(r3) : "r"(addr));
}
__device__ __forceinline__ void mma16816(float* c, const uint32_t* a, uint32_t b0, uint32_t b1) {
    asm volatile(
        "mma.sync.aligned.m16n8k16.row.col.f32.f16.f16.f32 "
        "{%0,%1,%2,%3}, {%4,%5,%6,%7}, {%8,%9}, {%0,%1,%2,%3};"
        : "+f"(c[0]), "+f"(c[1]), "+f"(c[2]), "+f"(c[3])
        : "r"(a[0]), "r"(a[1]), "r"(a[2]), "r"(a[3]), "r"(b0), "r"(b1));
}
__device__ __forceinline__ uint32_t packh2(float a, float b) {
    __half2 h = __floats2half2_rn(a, b);
    return *(uint32_t*)&h;
}

// ==================================================================
// GEMM tile body (BM=128, BN=128, BK=64, 3-stage cp.async, 256 thr)
// ==================================================================
#define GEMM_STAGE 36864
#define GEMM_SMEM  (3 * GEMM_STAGE)
#define GEMM_BOFF  18432

__device__ __forceinline__ void cp_stage_g(uint32_t sbase,
    const __half* __restrict__ A, const __half* __restrict__ B,
    int m0, int n0, int k0, int K, int tid)
{
#pragma unroll
    for (int j = 0; j < 4; j++) {
        int idx = tid + 256 * j;
        int row = idx >> 3;
        int c = idx & 7;
        uint32_t d = (uint32_t)(row * 144 + c * 16);
        cp16(sbase + d,             A + (size_t)(m0 + row) * K + k0 + c * 8);
        cp16(sbase + GEMM_BOFF + d, B + (size_t)(n0 + row) * K + k0 + c * 8);
    }
}

template<bool RELU, bool HOUT>
__device__ __forceinline__ void gemm_body(
    const __half* __restrict__ A, const __half* __restrict__ B,
    const float* __restrict__ bias, int biasRow,
    const float* __restrict__ resid,
    void* __restrict__ Cout, int M, int N, int K, int m0, int n0, uint32_t sb)
{
    const int tid = threadIdx.x;
    const int wid = tid >> 5;
    const int l = tid & 31;
    const int wm = (wid >> 1) * 32;
    const int wn = (wid & 1) * 64;
    const int KT = K >> 6;

    float c[2][8][4];
#pragma unroll
    for (int i = 0; i < 2; i++)
#pragma unroll
        for (int j = 0; j < 8; j++)
#pragma unroll
            for (int r = 0; r < 4; r++) c[i][j][r] = 0.f;

#pragma unroll
    for (int s = 0; s < 2; s++) {
        cp_stage_g(sb + s * GEMM_STAGE, A, B, m0, n0, s * 64, K, tid);
        CP_COMMIT();
    }

    const uint32_t aoff = (uint32_t)((wm + (l & 15)) * 144 + (l >> 4) * 16);
    const uint32_t boff = (uint32_t)((wn + (l & 7) + ((l >> 3) & 1) * 8) * 144 + (l >> 4) * 16);

    int stage = 0;
    for (int kt = 0; kt < KT; kt++) {
        asm volatile("cp.async.wait_group 1;" ::: "memory");
        __syncthreads();

        const int pf = kt + 2;
        int pstage = stage + 2; if (pstage >= 3) pstage -= 3;
        if (pf < KT) cp_stage_g(sb + pstage * GEMM_STAGE, A, B, m0, n0, pf * 64, K, tid);
        CP_COMMIT();

        const uint32_t sA = sb + stage * GEMM_STAGE;
        const uint32_t sB = sA + GEMM_BOFF;

#pragma unroll
        for (int kk = 0; kk < 4; kk++) {
            uint32_t a[2][4], b[4][4];
            ldsm4(a[0][0], a[0][1], a[0][2], a[0][3], sA + aoff + kk * 32);
            ldsm4(a[1][0], a[1][1], a[1][2], a[1][3], sA + aoff + 16 * 144 + kk * 32);
#pragma unroll
            for (int j = 0; j < 4; j++)
                ldsm4(b[j][0], b[j][1], b[j][2], b[j][3], sB + boff + j * 16 * 144 + kk * 32);
#pragma unroll
            for (int mi = 0; mi < 2; mi++)
#pragma unroll
                for (int nj = 0; nj < 8; nj++)
                    mma16816(c[mi][nj], a[mi], b[nj >> 1][nj & 1], b[nj >> 1][(nj & 1) + 2]);
        }
        if (++stage == 3) stage = 0;
    }

    const int row0 = m0 + wm + (l >> 2);
    const int colb = n0 + wn + (l & 3) * 2;
#pragma unroll
    for (int mi = 0; mi < 2; mi++) {
        const int r0 = row0 + mi * 16;
        float br0 = 0.f, br1 = 0.f;
        if (biasRow) { br0 = bias[r0]; br1 = bias[r0 + 8]; }
#pragma unroll
        for (int nj = 0; nj < 8; nj++) {
            const int col = colb + nj * 8;
            float b0, b1, b2, b3;
            if (biasRow) {
                b0 = br0; b1 = br0; b2 = br1; b3 = br1;
            } else {
                b0 = bias[col]; b1 = bias[col + 1]; b2 = b0; b3 = b1;
            }
            float v0 = c[mi][nj][0] + b0;
            float v1 = c[mi][nj][1] + b1;
            float v2 = c[mi][nj][2] + b2;
            float v3 = c[mi][nj][3] + b3;
            if (RELU) {
                v0 = fmaxf(v0, 0.f); v1 = fmaxf(v1, 0.f);
                v2 = fmaxf(v2, 0.f); v3 = fmaxf(v3, 0.f);
            }
            if (HOUT) {
                __half* C = (__half*)Cout;
                *(__half2*)&C[(size_t)r0 * N + col]       = __floats2half2_rn(v0, v1);
                *(__half2*)&C[(size_t)(r0 + 8) * N + col] = __floats2half2_rn(v2, v3);
            } else {
                float* C = (float*)Cout;
                if (resid != nullptr) {
                    float2 x0 = *(const float2*)&resid[(size_t)r0 * N + col];
                    float2 x1 = *(const float2*)&resid[(size_t)(r0 + 8) * N + col];
                    v0 += x0.x; v1 += x0.y; v2 += x1.x; v3 += x1.y;
                }
                float2 p0; p0.x = v0; p0.y = v1;
                float2 p1; p1.x = v2; p1.y = v3;
                *(float2*)&C[(size_t)r0 * N + col] = p0;
                *(float2*)&C[(size_t)(r0 + 8) * N + col] = p1;
            }
        }
    }
}

// ==================================================================
// Distributed LN tail (8 col-tile CTAs per 128-row block).
// ==================================================================
__device__ __forceinline__ void ln_tail(
    const float* __restrict__ T, int m0, int nb,
    const float* __restrict__ gamma, const float* __restrict__ beta,
    float* __restrict__ xout, __half* __restrict__ x16out,
    int* __restrict__ cnt)
{
    __threadfence();
    __syncthreads();
    if (threadIdx.x == 0) {
        atomicAdd(cnt, 1);
        while (atomicAdd(cnt, 0) < 8) { }
    }
    __syncthreads();
    __threadfence();

    const int w = threadIdx.x >> 5;
    const int l = threadIdx.x & 31;
    const int rbase = m0 + nb * 16;
#pragma unroll
    for (int i = 0; i < 2; i++) {
        const int row = rbase + w * 2 + i;
        const float* tr = T + (size_t)row * Dc;
        float4 v[8];
        float s = 0.f, ss = 0.f;
#pragma unroll
        for (int j = 0; j < 8; j++) {
            v[j] = *(const float4*)&tr[l * 4 + j * 128];
            s  += v[j].x + v[j].y + v[j].z + v[j].w;
            ss += v[j].x * v[j].x + v[j].y * v[j].y + v[j].z * v[j].z + v[j].w * v[j].w;
        }
#pragma unroll
        for (int o = 16; o > 0; o >>= 1) {
            s  += __shfl_xor_sync(0xffffffffu, s, o);
            ss += __shfl_xor_sync(0xffffffffu, ss, o);
        }
        const float mean = s * (1.f / Dc);
        const float var = ss * (1.f / Dc) - mean * mean;
        const float inv = rsqrtf(var + EPSc);
#pragma unroll
        for (int j = 0; j < 8; j++) {
            const int c = l * 4 + j * 128;
            float4 g4 = *(const float4*)&gamma[c];
            float4 b4 = *(const float4*)&beta[c];
            float4 o4;
            o4.x = g4.x * (v[j].x - mean) * inv + b4.x;
            o4.y = g4.y * (v[j].y - mean) * inv + b4.y;
            o4.z = g4.z * (v[j].z - mean) * inv + b4.z;
            o4.w = g4.w * (v[j].w - mean) * inv + b4.w;
            *(float4*)&xout[(size_t)row * Dc + c] = o4;
            *(__half2*)&x16out[(size_t)row * Dc + c]     = __floats2half2_rn(o4.x, o4.y);
            *(__half2*)&x16out[(size_t)row * Dc + c + 2] = __floats2half2_rn(o4.z, o4.w);
        }
    }
}

// ==================================================================
// Fused GEMM (+residual) + distributed LayerNorm. Grid (8,32)=256 CTAs.
// ==================================================================
__global__ void __launch_bounds__(256, 2)
gemm_ln_kernel(const __half* __restrict__ A, const __half* __restrict__ B,
               const float* __restrict__ bias, const float* __restrict__ resid,
               float* __restrict__ T, int M, int K,
               const float* __restrict__ gamma, const float* __restrict__ beta,
               float* __restrict__ xout, __half* __restrict__ x16out,
               int* __restrict__ cnt)
{
    extern __shared__ char sm_[];
    const uint32_t sb = smem_u32(sm_);
    const int m0 = blockIdx.y * 128;
    gemm_body<false, false>(A, B, bias, 0, resid, T,
                            M, Dc, K, m0, blockIdx.x * 128, sb);
    ln_tail(T, m0, blockIdx.x, gamma, beta, xout, x16out, &cnt[blockIdx.y]);
}

// ==================================================================
// Fused FFN: 1280 CTAs (FFN1 producers + FFN2/LN consumers).
// ==================================================================
__global__ void __launch_bounds__(256, 2)
ffn_mega_kernel(const __half* __restrict__ x16in,
                const __half* __restrict__ W1t, const float* __restrict__ B1,
                __half* __restrict__ ff,
                const __half* __restrict__ W2t, const float* __restrict__ B2,
                const float* __restrict__ resid, float* __restrict__ T,
                const float* __restrict__ gamma, const float* __restrict__ beta,
                float* __restrict__ xout, __half* __restrict__ x16out,
                int* __restrict__ ffcnt, int* __restrict__ lncnt)
{
    extern __shared__ char sm_[];
    const uint32_t sb = smem_u32(sm_);
    const int i = blockIdx.x;
    if (i < 1024) {
        const int mb = i >> 5;
        const int nb = i & 31;
        gemm_body<true, true>(x16in, W1t, B1, 0, nullptr, ff,
                              Mrows, FFc, Dc, mb * 128, nb * 128, sb);
        __threadfence();
        __syncthreads();
        if (threadIdx.x == 0) atomicAdd(&ffcnt[mb], 1);
    } else {
        const int j = i - 1024;
        const int mb = j >> 3;
        const int nb = j & 7;
        if (threadIdx.x == 0) {
            while (atomicAdd(&ffcnt[mb], 0) < 32) { __nanosleep(64); }
        }
        __syncthreads();
        __threadfence();
        gemm_body<false, false>(ff, W2t, B2, 0, resid, T,
                                Mrows, Dc, FFc, mb * 128, nb * 128, sb);
        ln_tail(T, mb * 128, nb, gamma, beta, xout, x16out, &lncnt[mb]);
    }
}

// ==================================================================
// Flash attention body (device function).
// ==================================================================
#define FL_K_OFF 18432
#define FL_V_OFF 9216
#define FL_SMEM (18432 + 2 * 18432)

__device__ __forceinline__ void flash_body(
    const __half* __restrict__ Qg, int qStride,
    const __half* __restrict__ Kg, int kStride,
    const __half* __restrict__ VTg, int vtStride,
    const __half* __restrict__ biasMask,
    __half* __restrict__ O, int q0, int bh, uint32_t sb)
{
    const int tid = threadIdx.x;
    const int wid = tid >> 5;
    const int l = tid & 31;
    const int b = bh >> 4;
    const int h = bh & 15;
    const int wm = wid * 16;

    const __half* Qb = Qg + h * DHc;
    const __half* Kb = Kg + h * DHc;
    const __half* VTb = VTg + (size_t)(h * DHc) * vtStride + b * Nc;

    const uint32_t sQ = sb;

#pragma unroll
    for (int j = 0; j < 4; j++) {
        int idx = tid + 256 * j;
        int row = idx >> 3;
        int c = idx & 7;
        cp16(sQ + (uint32_t)(row * 144 + c * 16),
             Qb + (size_t)(b * Nc + q0 + row) * qStride + c * 8);
    }
    {
        uint32_t sK = sb + FL_K_OFF;
        uint32_t sV = sK + FL_V_OFF;
#pragma unroll
        for (int j = 0; j < 2; j++) {
            int idx = tid + 256 * j;
            int row = idx >> 3;
            int c = idx & 7;
            cp16(sK + (uint32_t)(row * 144 + c * 16),
                 Kb + (size_t)(b * Nc + row) * kStride + c * 8);
            cp16(sV + (uint32_t)(row * 144 + c * 16),
                 VTb + (size_t)row * vtStride + c * 8);
        }
    }
    CP_COMMIT();

    float o[8][4];
#pragma unroll
    for (int j = 0; j < 8; j++)
#pragma unroll
        for (int r = 0; r < 4; r++) o[j][r] = 0.f;
    float mrow[2] = { -INFINITY, -INFINITY };
    float lsum[2] = { 0.f, 0.f };

    const uint32_t aoff = (uint32_t)((wm + (l & 15)) * 144 + (l >> 4) * 16);
    const uint32_t boff = (uint32_t)(((l & 7) + ((l >> 3) & 1) * 8) * 144 + (l >> 4) * 16);
    const int r0g = q0 + wm + (l >> 2);

    for (int t = 0; t < 8; t++) {
        if (t < 7) {
            uint32_t sK = sb + FL_K_OFF + ((t + 1) & 1) * FL_K_OFF;
            uint32_t sV = sK + FL_V_OFF;
            const int kv0 = (t + 1) * 64;
#pragma unroll
            for (int j = 0; j < 2; j++) {
                int idx = tid + 256 * j;
                int row = idx >> 3;
                int c = idx & 7;
                cp16(sK + (uint32_t)(row * 144 + c * 16),
                     Kb + (size_t)(b * Nc + kv0 + row) * kStride + c * 8);
                cp16(sV + (uint32_t)(row * 144 + c * 16),
                     VTb + (size_t)row * vtStride + kv0 + c * 8);
            }
            CP_COMMIT();
            asm volatile("cp.async.wait_group 1;" ::: "memory");
        } else {
            asm volatile("cp.async.wait_group 0;" ::: "memory");
        }
        __syncthreads();

        const uint32_t sK = sb + FL_K_OFF + (t & 1) * FL_K_OFF;
        const uint32_t sV = sK + FL_V_OFF;

        float s[8][4];
#pragma unroll
        for (int j = 0; j < 8; j++)
#pragma unroll
            for (int r = 0; r < 4; r++) s[j][r] = 0.f;

#pragma unroll
        for (int kk = 0; kk < 4; kk++) {
            uint32_t a[4], bf[4][4];
            ldsm4(a[0], a[1], a[2], a[3], sQ + aoff + kk * 32);
#pragma unroll
            for (int j = 0; j < 4; j++)
                ldsm4(bf[j][0], bf[j][1], bf[j][2], bf[j][3], sK + boff + j * 16 * 144 + kk * 32);
#pragma unroll
            for (int j = 0; j < 4; j++) {
                mma16816(s[2 * j],     a, bf[j][0], bf[j][2]);
                mma16816(s[2 * j + 1], a, bf[j][1], bf[j][3]);
            }
        }

        const int colb = t * 64 + (l & 3) * 2;
        if (biasMask != nullptr) {
#pragma unroll
            for (int nj = 0; nj < 8; nj++) {
                const int col = colb + nj * 8;
                __half2 b0 = *(const __half2*)&biasMask[((size_t)b * Nc + r0g) * Nc + col];
                __half2 b1 = *(const __half2*)&biasMask[((size_t)b * Nc + r0g + 8) * Nc + col];
                s[nj][0] = s[nj][0] * 0.125f + __low2float(b0);
                s[nj][1] = s[nj][1] * 0.125f + __high2float(b0);
                s[nj][2] = s[nj][2] * 0.125f + __low2float(b1);
                s[nj][3] = s[nj][3] * 0.125f + __high2float(b1);
            }
        } else {
#pragma unroll
            for (int nj = 0; nj < 8; nj++) {
                s[nj][0] *= 0.125f; s[nj][1] *= 0.125f;
                s[nj][2] *= 0.125f; s[nj][3] *= 0.125f;
            }
        }

        float m0 = -INFINITY, m1 = -INFINITY;
#pragma unroll
        for (int nj = 0; nj < 8; nj++) {
            m0 = fmaxf(m0, fmaxf(s[nj][0], s[nj][1]));
            m1 = fmaxf(m1, fmaxf(s[nj][2], s[nj][3]));
        }
        m0 = fmaxf(m0, __shfl_xor_sync(0xffffffffu, m0, 1));
        m0 = fmaxf(m0, __shfl_xor_sync(0xffffffffu, m0, 2));
        m1 = fmaxf(m1, __shfl_xor_sync(0xffffffffu, m1, 1));
        m1 = fmaxf(m1, __shfl_xor_sync(0xffffffffu, m1, 2));

        const float mn0 = fmaxf(mrow[0], m0);
        const float mn1 = fmaxf(mrow[1], m1);
        const float sc0 = __expf(mrow[0] - mn0);
        const float sc1 = __expf(mrow[1] - mn1);
        mrow[0] = mn0; mrow[1] = mn1;

        float rs0 = 0.f, rs1 = 0.f;
#pragma unroll
        for (int nj = 0; nj < 8; nj++) {
            s[nj][0] = __expf(s[nj][0] - mn0);
            s[nj][1] = __expf(s[nj][1] - mn0);
            s[nj][2] = __expf(s[nj][2] - mn1);
            s[nj][3] = __expf(s[nj][3] - mn1);
            rs0 += s[nj][0] + s[nj][1];
            rs1 += s[nj][2] + s[nj][3];
        }
        rs0 += __shfl_xor_sync(0xffffffffu, rs0, 1);
        rs0 += __shfl_xor_sync(0xffffffffu, rs0, 2);
        rs1 += __shfl_xor_sync(0xffffffffu, rs1, 1);
        rs1 += __shfl_xor_sync(0xffffffffu, rs1, 2);
        lsum[0] = lsum[0] * sc0 + rs0;
        lsum[1] = lsum[1] * sc1 + rs1;

#pragma unroll
        for (int j = 0; j < 8; j++) {
            o[j][0] *= sc0; o[j][1] *= sc0;
            o[j][2] *= sc1; o[j][3] *= sc1;
        }

#pragma unroll
        for (int kk = 0; kk < 4; kk++) {
            uint32_t a[4];
            a[0] = packh2(s[2 * kk][0],     s[2 * kk][1]);
            a[1] = packh2(s[2 * kk][2],     s[2 * kk][3]);
            a[2] = packh2(s[2 * kk + 1][0], s[2 * kk + 1][1]);
            a[3] = packh2(s[2 * kk + 1][2], s[2 * kk + 1][3]);
            uint32_t bf[4][4];
#pragma unroll
            for (int j = 0; j < 4; j++)
                ldsm4(bf[j][0], bf[j][1], bf[j][2], bf[j][3], sV + boff + j * 16 * 144 + kk * 32);
#pragma unroll
            for (int j = 0; j < 4; j++) {
                mma16816(o[2 * j],     a, bf[j][0], bf[j][2]);
                mma16816(o[2 * j + 1], a, bf[j][1], bf[j][3]);
            }
        }
        __syncthreads();
    }

    const float inv0 = 1.f / lsum[0];
    const float inv1 = 1.f / lsum[1];
#pragma unroll
    for (int njo = 0; njo < 8; njo++) {
        const int gc = h * DHc + njo * 8 + (l & 3) * 2;
        *(__half2*)&O[(size_t)(b * Nc + r0g) * Dc + gc] =
            __floats2half2_rn(o[njo][0] * inv0, o[njo][1] * inv0);
        *(__half2*)&O[(size_t)(b * Nc + r0g + 8) * Dc + gc] =
            __floats2half2_rn(o[njo][2] * inv1, o[njo][3] * inv1);
    }
}

// ==================================================================
// Fused attention: 1280 CTAs, fine-grained per-batch dependency.
//  bid<512:  QK tile; signals sync[batch = bid>>6]
//  bid<768:  VT tile; signals sync[(j&31)>>2]
//  bid>=768: flash for (q0, bh); spins sync[b] == 96 (64 QK + 32 VT)
// Producers never wait; consumers have higher bids -> no deadlock.
// ==================================================================
__global__ void __launch_bounds__(256, 2)
attn_mega_kernel(const __half* __restrict__ Aq, const __half* __restrict__ Aq2, int nSplit,
                 const __half* __restrict__ Wqk, const float* __restrict__ biasQK,
                 __half* __restrict__ qkOut,
                 const __half* __restrict__ Wv, const __half* __restrict__ Bv,
                 const float* __restrict__ biasV, __half* __restrict__ vtOut,
                 const __half* __restrict__ biasMask, __half* __restrict__ O,
                 int* __restrict__ sync)
{
    extern __shared__ char sm_[];
    const uint32_t sb = smem_u32(sm_);
    const int i = blockIdx.x;
    if (i < 512) {
        const int m0 = (i >> 4) * 128;
        const int n0 = (i & 15) * 128;
        const __half* Au = (n0 >= nSplit) ? Aq2 : Aq;
        gemm_body<false, true>(Au, Wqk, biasQK, 0, nullptr, qkOut,
                               Mrows, 2 * Dc, Dc, m0, n0, sb);
        __threadfence();
        __syncthreads();
        if (threadIdx.x == 0) atomicAdd(&sync[i >> 6], 1);
    } else if (i < 768) {
        const int j = i - 512;
        const int n0 = (j & 31) * 128;
        const int m0 = (j >> 5) * 128;
        gemm_body<false, true>(Wv, Bv, biasV, 1, nullptr, vtOut,
                               Dc, Mrows, Dc, m0, n0, sb);
        __threadfence();
        __syncthreads();
        if (threadIdx.x == 0) atomicAdd(&sync[(j & 31) >> 2], 1);
    } else {
        const int j = i - 768;
        const int q0 = (j & 3) * 128;
        const int bh = j >> 2;
        const int b = bh >> 4;
        if (threadIdx.x == 0) {
            while (atomicAdd(&sync[b], 0) < 96) { __nanosleep(64); }
        }
        __syncthreads();
        __threadfence();
        flash_body(qkOut, 2 * Dc, qkOut + Dc, 2 * Dc, vtOut, Mrows,
                   biasMask, O, q0, bh, sb);
    }
}

// ==================================================================
// Mask -> fp16 additive bias (0 / -10000)
// ==================================================================
__global__ void __launch_bounds__(256)
maskbias_kernel(const int* __restrict__ mask, __half* __restrict__ bias, int n)
{
    int i = (blockIdx.x * 256 + threadIdx.x) * 4;
    if (i >= n) return;
    int4 m = *(const int4*)(mask + i);
    __half z = __float2half(0.f), neg = __float2half(-10000.f);
    bias[i]     = m.x ? z : neg;
    bias[i + 1] = m.y ? z : neg;
    bias[i + 2] = m.z ? z : neg;
    bias[i + 3] = m.w ? z : neg;
}

// ==================================================================
// All weight transposes in ONE launch (24576 tiles of 64x64)
// ==================================================================
__device__ __forceinline__ void wt_tile(
    const float* __restrict__ W, __half* __restrict__ T,
    int K, int N, int k0, int n0)
{
    __shared__ float t[64][65];
    const int tid = threadIdx.x;
#pragma unroll
    for (int j = 0; j < 4; j++) {
        int idx = tid + 256 * j;
        int row = idx >> 4;
        int c = (idx & 15) * 4;
        float4 v = *(const float4*)&W[(size_t)(k0 + row) * N + n0 + c];
        t[row][c + 0] = v.x; t[row][c + 1] = v.y;
        t[row][c + 2] = v.z; t[row][c + 3] = v.w;
    }
    __syncthreads();
#pragma unroll
    for (int j = 0; j < 8; j++) {
        int idx = tid + 256 * j;
        int n = idx >> 5;
        int kp = idx & 31;
        __half2 h = __floats2half2_rn(t[2 * kp][n], t[2 * kp + 1][n]);
        *(__half2*)&T[(size_t)(n0 + n) * K + k0 + 2 * kp] = h;
    }
}

__global__ void __launch_bounds__(256)
wt_all_kernel(const float* __restrict__ sa_w, __half* __restrict__ wsa,
              const float* __restrict__ ca_w, __half* __restrict__ wca,
              const float* __restrict__ w1, __half* __restrict__ w1t,
              const float* __restrict__ w2, __half* __restrict__ w2t)
{
    const int i = blockIdx.x;
    if (i < 6144) {
        int z = i >> 8, r = i & 255;
        wt_tile(sa_w + (size_t)z * Dc * Dc, wsa + (size_t)z * Dc * Dc,
                Dc, Dc, (r >> 4) * 64, (r & 15) * 64);
    } else if (i < 12288) {
        int j = i - 6144;
        int z = j >> 8, r = j & 255;
        wt_tile(ca_w + (size_t)z * Dc * Dc, wca + (size_t)z * Dc * Dc,
                Dc, Dc, (r >> 4) * 64, (r & 15) * 64);
    } else if (i < 18432) {
        int j = i - 12288;
        int z = j >> 10, r = j & 1023;
        wt_tile(w1 + (size_t)z * Dc * FFc, w1t + (size_t)z * Dc * FFc,
                Dc, FFc, (r >> 6) * 64, (r & 63) * 64);
    } else {
        int j = i - 18432;
        int z = j >> 10, r = j & 1023;
        wt_tile(w2 + (size_t)z * FFc * Dc, w2t + (size_t)z * FFc * Dc,
                FFc, Dc, (r >> 4) * 64, (r & 15) * 64);
    }
}

// ------------------------------------------------------------------
// misc
// ------------------------------------------------------------------
__global__ void __launch_bounds__(256)
initx_kernel(const float* __restrict__ in, float* __restrict__ x,
             __half* __restrict__ x16, int n)
{
    int i = (blockIdx.x * 256 + threadIdx.x) * 4;
    if (i >= n) return;
    float4 v = *(const float4*)(in + i);
    *(float4*)(x + i) = v;
    *(__half2*)(x16 + i)     = __floats2half2_rn(v.x, v.y);
    *(__half2*)(x16 + i + 2) = __floats2half2_rn(v.z, v.w);
}
__global__ void __launch_bounds__(256)
f2h_kernel(const float* __restrict__ in, __half* __restrict__ out, int n)
{
    int i = (blockIdx.x * 256 + threadIdx.x) * 4;
    if (i >= n) return;
    float4 v = *(const float4*)(in + i);
    *(__half2*)(out + i)     = __floats2half2_rn(v.x, v.y);
    *(__half2*)(out + i + 2) = __floats2half2_rn(v.z, v.w);
}

// ------------------------------------------------------------------
// Host orchestration
// ------------------------------------------------------------------
extern "C" void kernel_launch(void* const* d_in, const int* in_sizes, int n_in,
                              void* d_out, int out_size)
{
    const float* trg  = (const float*)d_in[0];
    const float* enc  = (const float*)d_in[1];
    const int*   mask = (const int*)  d_in[2];
    const float* sa_w = (const float*)d_in[3];
    const float* sa_b = (const float*)d_in[4];
    const float* ca_w = (const float*)d_in[5];
    const float* ca_b = (const float*)d_in[6];
    const float* ln_g = (const float*)d_in[7];
    const float* ln_b = (const float*)d_in[8];
    const float* w1   = (const float*)d_in[9];
    const float* b1   = (const float*)d_in[10];
    const float* w2   = (const float*)d_in[11];
    const float* b2   = (const float*)d_in[12];
    float* out = (float*)d_out;

    float *x, *t;
    __half *x16, *e16, *qk16, *vt16, *ao16, *ff16, *bias16;
    __half *wsa, *wca, *w1t, *w2t;
    int *cnt, *ffcnt, *async;
    cudaGetSymbolAddress((void**)&x,  g_x);
    cudaGetSymbolAddress((void**)&t,  g_t);
    cudaGetSymbolAddress((void**)&x16, g_x16);
    cudaGetSymbolAddress((void**)&e16, g_e16);
    cudaGetSymbolAddress((void**)&qk16, g_qk16);
    cudaGetSymbolAddress((void**)&vt16, g_vt16);
    cudaGetSymbolAddress((void**)&ao16, g_ao16);
    cudaGetSymbolAddress((void**)&ff16, g_ff16);
    cudaGetSymbolAddress((void**)&bias16, g_bias16);
    cudaGetSymbolAddress((void**)&wsa, g_wsa);
    cudaGetSymbolAddress((void**)&wca, g_wca);
    cudaGetSymbolAddress((void**)&w1t, g_w1t);
    cudaGetSymbolAddress((void**)&w2t, g_w2t);
    cudaGetSymbolAddress((void**)&cnt, g_cnt);
    cudaGetSymbolAddress((void**)&ffcnt, g_ffcnt);
    cudaGetSymbolAddress((void**)&async, g_async);

    cudaFuncSetAttribute(gemm_ln_kernel, cudaFuncAttributeMaxDynamicSharedMemorySize, GEMM_SMEM);
    cudaFuncSetAttribute(ffn_mega_kernel, cudaFuncAttributeMaxDynamicSharedMemorySize, GEMM_SMEM);
    cudaFuncSetAttribute(attn_mega_kernel, cudaFuncAttributeMaxDynamicSharedMemorySize, GEMM_SMEM);

    cudaMemsetAsync(cnt, 0, 18 * 32 * sizeof(int));
    cudaMemsetAsync(ffcnt, 0, 6 * 32 * sizeof(int));
    cudaMemsetAsync(async, 0, 12 * 8 * sizeof(int));

    const int nElem = Mrows * Dc;
    initx_kernel<<<(nElem / 4 + 255) / 256, 256>>>(trg, x, x16, nElem);
    f2h_kernel<<<(nElem / 4 + 255) / 256, 256>>>(enc, e16, nElem);
    const int nMask = Bc * Nc * Nc;
    maskbias_kernel<<<(nMask / 4 + 255) / 256, 256>>>(mask, bias16, nMask);
    wt_all_kernel<<<24576, 256>>>(sa_w, wsa, ca_w, wca, w1, w1t, w2, w2t);

    dim3 gProj(Dc / 128, Mrows / 128);       // (8, 32)
    const int gAttn = 1280;
    const int gFFN = 1280;

    int callIdx = 0, syncIdx = 0;
    for (int l = 0; l < Lc; l++) {
        const __half* Ws = wsa + (size_t)l * 4 * Dc * Dc;
        const __half* Wc = wca + (size_t)l * 4 * Dc * Dc;
        const float* Bs = sa_b + (size_t)l * 4 * Dc;
        const float* Bcp = ca_b + (size_t)l * 4 * Dc;
        float* xOutFF = (l == Lc - 1) ? out : x;

        // ===== self-attention (prep + flash, per-batch counters) =====
        attn_mega_kernel<<<gAttn, 256, GEMM_SMEM>>>(
            x16, x16, 1 << 28, Ws, Bs, qk16,
            Ws + 2 * Dc * Dc, x16, Bs + 2 * Dc, vt16,
            bias16, ao16, async + (syncIdx++) * 8);
        gemm_ln_kernel<<<gProj, 256, GEMM_SMEM>>>(
            ao16, Ws + 3 * Dc * Dc, Bs + 3 * Dc, x, t, Mrows, Dc,
            ln_g + ((size_t)l * 3 + 0) * Dc, ln_b + ((size_t)l * 3 + 0) * Dc, x, x16, cnt + (callIdx++) * 32);

        // ===== cross-attention =====
        attn_mega_kernel<<<gAttn, 256, GEMM_SMEM>>>(
            x16, e16, Dc, Wc, Bcp, qk16,
            Wc + 2 * Dc * Dc, e16, Bcp + 2 * Dc, vt16,
            nullptr, ao16, async + (syncIdx++) * 8);
        gemm_ln_kernel<<<gProj, 256, GEMM_SMEM>>>(
            ao16, Wc + 3 * Dc * Dc, Bcp + 3 * Dc, x, t, Mrows, Dc,
            ln_g + ((size_t)l * 3 + 1) * Dc, ln_b + ((size_t)l * 3 + 1) * Dc, x, x16, cnt + (callIdx++) * 32);

        // ===== FFN =====
        ffn_mega_kernel<<<gFFN, 256, GEMM_SMEM>>>(
            x16, w1t + (size_t)l * Dc * FFc, b1 + (size_t)l * FFc, ff16,
            w2t + (size_t)l * FFc * Dc, b2 + (size_t)l * Dc, x, t,
            ln_g + ((size_t)l * 3 + 2) * Dc, ln_b + ((size_t)l * 3 + 2) * Dc,
            xOutFF, x16, ffcnt + l * 32, cnt + (callIdx++) * 32);
    }
}